// round 10
// baseline (speedup 1.0000x reference)
#include <cuda_runtime.h>
#include <cuda_fp16.h>
#include <cstdint>

// Problem dims (fixed by setup_inputs)
#define BATCH 4
#define NG 64
#define NH 8
#define NP 4096
#define PCHUNK 256
#define TILE 16

struct __align__(16) Smem {
    uint2  Bp[8][8][32];      // W2' = diag(g1)*W2 fp16 frags            16 KB
    uint2  W1p[16][32];       // W1' = [W1;b1;0] 2-term fp16 k8 frags     4 KB
    float4 sp[PCHUNK];        // scene points                             4 KB
    uint4  bDp[4][32];        // stage-D A3 frags {h0,h1,l0,l1}           2 KB
    uint2  GEp[8][4];         // {G, EB} fp16x2 per (nb, t)              256 B
};                             // ~26.3 KB total -> 3 blocks/SM

// fp16 split: hi + residual lo, packed fp16x2 (x0 low).
__device__ __forceinline__ void split2h(float x0, float x1, unsigned& hi, unsigned& lo) {
    asm("cvt.rn.f16x2.f32 %0, %1, %2;" : "=r"(hi) : "f"(x1), "f"(x0));
    __half2 hv = *reinterpret_cast<__half2*>(&hi);
    float2 back = __half22float2(hv);
    asm("cvt.rn.f16x2.f32 %0, %1, %2;" : "=r"(lo) : "f"(x1 - back.y), "f"(x0 - back.x));
}
__device__ __forceinline__ unsigned pack_h2(float x0, float x1) {
    unsigned u;
    asm("cvt.rn.f16x2.f32 %0, %1, %2;" : "=r"(u) : "f"(x1), "f"(x0));
    return u;
}
__device__ __forceinline__ float2 unpack_h2(unsigned u) {
    return __half22float2(*reinterpret_cast<__half2*>(&u));
}
__device__ __forceinline__ void mma_f16(float d[4], const unsigned a[4],
                                        unsigned b0, unsigned b1) {
    asm volatile(
        "mma.sync.aligned.m16n8k16.row.col.f32.f16.f16.f32 "
        "{%0,%1,%2,%3},{%4,%5,%6,%7},{%8,%9},{%0,%1,%2,%3};"
        : "+f"(d[0]), "+f"(d[1]), "+f"(d[2]), "+f"(d[3])
        : "r"(a[0]), "r"(a[1]), "r"(a[2]), "r"(a[3]), "r"(b0), "r"(b1));
}
__device__ __forceinline__ void mma_f16_k8(float d[4], unsigned a0, unsigned a1,
                                           unsigned b0) {
    asm volatile(
        "mma.sync.aligned.m16n8k8.row.col.f32.f16.f16.f32 "
        "{%0,%1,%2,%3},{%4,%5},{%6},{%0,%1,%2,%3};"
        : "+f"(d[0]), "+f"(d[1]), "+f"(d[2]), "+f"(d[3])
        : "r"(a0), "r"(a1), "r"(b0));
}

__global__ void __launch_bounds__(256, 3)
gab_kernel(const float* __restrict__ scene,   // (B, NP, 3)
           const float* __restrict__ poses,   // (B, NG, 7)
           const float* __restrict__ W1, const float* __restrict__ b1,
           const float* __restrict__ g1, const float* __restrict__ be1,
           const float* __restrict__ W2, const float* __restrict__ b2,
           const float* __restrict__ g2, const float* __restrict__ be2,
           const float* __restrict__ W3, const float* __restrict__ b3,
           const float* __restrict__ bscale,
           float* __restrict__ out)            // (B, NH, NG, NP)
{
    extern __shared__ __align__(16) char smraw[];
    Smem& sm = *reinterpret_cast<Smem*>(smraw);

    const int tid = threadIdx.x;
    const int b = blockIdx.z;
    const int gbase = blockIdx.y * 8;
    const int p0 = blockIdx.x * PCHUNK;

    // ---- Prologue ----
    for (int idx = tid; idx < 8 * 8 * 32; idx += 256) {
        int kb = idx >> 8, rem = idx & 255;
        int nb = rem >> 5, ln = rem & 31;
        int tt = ln & 3, c = ln >> 2;
        int n = nb * 8 + c;
        int k0 = kb * 16 + 2 * tt;
        unsigned hi0 = pack_h2(g1[k0 + 0] * W2[(k0 + 0) * 64 + n],
                               g1[k0 + 1] * W2[(k0 + 1) * 64 + n]);
        unsigned hi1 = pack_h2(g1[k0 + 8] * W2[(k0 + 8) * 64 + n],
                               g1[k0 + 9] * W2[(k0 + 9) * 64 + n]);
        sm.Bp[kb][nb][ln] = make_uint2(hi0, hi1);
    }
    for (int idx = tid; idx < 16 * 32; idx += 256) {
        int nb = idx >> 5, ln = idx & 31;
        int tt = ln & 3, c = ln >> 2;
        int n = nb * 8 + c;
        int k0 = 2 * tt, k1 = 2 * tt + 1;
        float w0 = (k0 < 4) ? W1[k0 * 128 + n] : (k0 == 4 ? b1[n] : 0.f);
        float w1 = (k1 < 4) ? W1[k1 * 128 + n] : (k1 == 4 ? b1[n] : 0.f);
        unsigned hi, lo;
        split2h(w0, w1, hi, lo);
        sm.W1p[nb][ln] = make_uint2(hi, lo);
    }
    if (tid < 128) {      // stage-D A3 fragments
        int kb2 = tid >> 5, ln = tid & 31;
        int tt = ln & 3, gg2 = ln >> 2;
        int k0 = kb2 * 16 + 2 * tt;
        float a0 = g2[k0 + 0] * W3[(k0 + 0) * 8 + gg2];
        float a1 = g2[k0 + 1] * W3[(k0 + 1) * 8 + gg2];
        float a2 = g2[k0 + 8] * W3[(k0 + 8) * 8 + gg2];
        float a3 = g2[k0 + 9] * W3[(k0 + 9) * 8 + gg2];
        unsigned h0, l0, h1, l1;
        split2h(a0, a1, h0, l0);
        split2h(a2, a3, h1, l1);
        sm.bDp[kb2][ln] = make_uint4(h0, h1, l0, l1);
    }
    if (tid >= 128 && tid < 160) {   // G/EB fold vectors
        int j = tid - 128;
        int nb = j >> 2, tt = j & 3;
        int n0 = nb * 8 + 2 * tt, n1 = n0 + 1;
        float G0 = 0.f, G1 = 0.f, E0 = 0.f, E1 = 0.f;
        #pragma unroll 4
        for (int k = 0; k < 128; ++k) {
            float gk = g1[k], bk = be1[k];
            float w0 = W2[k * 64 + n0], w1 = W2[k * 64 + n1];
            G0 = fmaf(gk, w0, G0); G1 = fmaf(gk, w1, G1);
            E0 = fmaf(bk, w0, E0); E1 = fmaf(bk, w1, E1);
        }
        sm.GEp[nb][tt] = make_uint2(pack_h2(G0, G1),
                                    pack_h2(E0 + b2[n0], E1 + b2[n1]));
    }
    if (tid < PCHUNK) {
        const float* spp = scene + ((size_t)b * NP + p0 + tid) * 3;
        sm.sp[tid] = make_float4(spp[0], spp[1], spp[2], 0.f);
    }
    __syncthreads();

    const int wid = tid >> 5, lane = tid & 31;
    const int g = gbase + wid;
    const int t = lane & 3, gg = lane >> 2;   // mma fragment coords

    // ---- Per-head fold constants for heads h0 = 2t, h1 = 2t+1 ----
    float K2a = 0.f, K2b = 0.f, K1a = 0.f, K1b = 0.f;
    #pragma unroll 8
    for (int c = 0; c < 64; ++c) {
        float2 w = *reinterpret_cast<const float2*>(W3 + c * 8 + 2 * t);
        float gc = __ldg(g2 + c), bc = __ldg(be2 + c);
        K2a = fmaf(gc, w.x, K2a); K2b = fmaf(gc, w.y, K2b);
        K1a = fmaf(bc, w.x, K1a); K1b = fmaf(bc, w.y, K1b);
    }
    const float bsa = __ldg(bscale + 2 * t), bsb = __ldg(bscale + 2 * t + 1);
    const float C0a = (K1a + __ldg(b3 + 2 * t)) * bsa;
    const float C0b = (K1b + __ldg(b3 + 2 * t + 1)) * bsb;

    // Per-warp pose -> rotation
    const float* pp = poses + ((size_t)(b * NG + g)) * 7;
    float tx = pp[0], ty = pp[1], tz = pp[2];
    float qx = pp[3], qy = pp[4], qz = pp[5], qw = pp[6];
    float inv = 1.f / (sqrtf(qx * qx + qy * qy + qz * qz + qw * qw) + 1e-8f);
    qx *= inv; qy *= inv; qz *= inv; qw *= inv;
    float xx = qx * qx, yy = qy * qy, zz = qz * qz;
    float xy = qx * qy, xz = qx * qz, yz = qy * qz;
    float wx = qw * qx, wy = qw * qy, wz = qw * qz;
    float R00 = 1.f - 2.f * (yy + zz), R01 = 2.f * (xy - wz), R02 = 2.f * (xz + wy);
    float R10 = 2.f * (xy + wz), R11 = 1.f - 2.f * (xx + zz), R12 = 2.f * (yz - wx);
    float R20 = 2.f * (xz - wy), R21 = 2.f * (yz + wx), R22 = 1.f - 2.f * (xx + yy);

    const size_t outbase = (((size_t)b * NH) * NG + g) * NP + p0;

    for (int it = 0; it < PCHUNK / TILE; ++it) {
        // ---- Geometry for this lane's two rows (gg, gg+8) ----
        float4 PA = sm.sp[it * TILE + gg];
        float4 PB = sm.sp[it * TILE + gg + 8];
        float rxA = PA.x - tx, ryA = PA.y - ty, rzA = PA.z - tz;
        float lxA = R00 * rxA + R10 * ryA + R20 * rzA;
        float lyA = R01 * rxA + R11 * ryA + R21 * rzA;
        float lzA = R02 * rxA + R12 * ryA + R22 * rzA;
        float ddA = sqrtf(lxA * lxA + lyA * lyA + lzA * lzA);
        float rxB = PB.x - tx, ryB = PB.y - ty, rzB = PB.z - tz;
        float lxB = R00 * rxB + R10 * ryB + R20 * rzB;
        float lyB = R01 * rxB + R11 * ryB + R21 * rzB;
        float lzB = R02 * rxB + R12 * ryB + R22 * rzB;
        float ddB = sqrtf(lxB * lxB + lyB * lyB + lzB * lzB);
        // A-frag (m16n8k8): k cols 2t,2t+1 of feats = (lx,ly,lz,dd,1,0,0,0)
        float s0A = (t == 0) ? lxA : (t == 1) ? lzA : (t == 2) ? 1.f : 0.f;
        float s1A = (t == 0) ? lyA : (t == 1) ? ddA : 0.f;
        float s0B = (t == 0) ? lxB : (t == 1) ? lzB : (t == 2) ? 1.f : 0.f;
        float s1B = (t == 0) ? lyB : (t == 1) ? ddB : 0.f;
        unsigned af0 = pack_h2(s0A, s1A);
        unsigned af1 = pack_h2(s0B, s1B);

        // ---- Fused stages B+C: per kb, make afr then consume it ----
        float d[8][4];
        #pragma unroll
        for (int nb = 0; nb < 8; ++nb) { d[nb][0] = d[nb][1] = d[nb][2] = d[nb][3] = 0.f; }
        float sA = 0.f, qA = 0.f, sB = 0.f, qB = 0.f;

        #pragma unroll 2
        for (int kb = 0; kb < 8; ++kb) {
            uint2 wb0 = sm.W1p[2 * kb][lane];
            uint2 wb1 = sm.W1p[2 * kb + 1][lane];
            float d0[4] = {0.f, 0.f, 0.f, 0.f};
            float d1[4] = {0.f, 0.f, 0.f, 0.f};
            mma_f16_k8(d0, af0, af1, wb0.x);
            mma_f16_k8(d0, af0, af1, wb0.y);
            mma_f16_k8(d1, af0, af1, wb1.x);
            mma_f16_k8(d1, af0, af1, wb1.y);
            float v0 = fmaxf(d0[0], 0.f), v1 = fmaxf(d0[1], 0.f);
            float v2 = fmaxf(d0[2], 0.f), v3 = fmaxf(d0[3], 0.f);
            float v4 = fmaxf(d1[0], 0.f), v5 = fmaxf(d1[1], 0.f);
            float v6 = fmaxf(d1[2], 0.f), v7 = fmaxf(d1[3], 0.f);
            sA += (v0 + v1) + (v4 + v5);
            qA = fmaf(v0, v0, fmaf(v1, v1, fmaf(v4, v4, fmaf(v5, v5, qA))));
            sB += (v2 + v3) + (v6 + v7);
            qB = fmaf(v2, v2, fmaf(v3, v3, fmaf(v6, v6, fmaf(v7, v7, qB))));
            unsigned afr[4];
            afr[0] = pack_h2(v0, v1);
            afr[1] = pack_h2(v2, v3);
            afr[2] = pack_h2(v4, v5);
            afr[3] = pack_h2(v6, v7);
            #pragma unroll
            for (int nb = 0; nb < 8; ++nb) {
                uint2 bp = sm.Bp[kb][nb][lane];
                mma_f16(d[nb], afr, bp.x, bp.y);
            }
        }
        // LN1 stats over 128 cols: reduce across t-quad
        #pragma unroll
        for (int o = 1; o <= 2; o <<= 1) {
            sA += __shfl_xor_sync(0xffffffffu, sA, o);
            qA += __shfl_xor_sync(0xffffffffu, qA, o);
            sB += __shfl_xor_sync(0xffffffffu, sB, o);
            qB += __shfl_xor_sync(0xffffffffu, qB, o);
        }
        float mu1A = sA * (1.f / 128.f);
        float rs1A = rsqrtf(fmaxf(qA * (1.f / 128.f) - mu1A * mu1A, 0.f) + 1e-5f);
        float ng1A = -mu1A * rs1A;
        float mu1B = sB * (1.f / 128.f);
        float rs1B = rsqrtf(fmaxf(qB * (1.f / 128.f) - mu1B * mu1B, 0.f) + 1e-5f);
        float ng1B = -mu1B * rs1B;

        // ---- Epilogue (LN1-fold) + Stage D chaining ----
        float ddd[4] = {0.f, 0.f, 0.f, 0.f};
        float sg = 0.f, qg = 0.f, sh = 0.f, qh = 0.f;
        #pragma unroll
        for (int kb2 = 0; kb2 < 4; ++kb2) {
            const int nb0 = 2 * kb2, nb1 = 2 * kb2 + 1;
            uint2 ge0 = sm.GEp[nb0][t];
            uint2 ge1 = sm.GEp[nb1][t];
            float2 G0 = unpack_h2(ge0.x), E0 = unpack_h2(ge0.y);
            float2 G1 = unpack_h2(ge1.x), E1 = unpack_h2(ge1.y);
            // v = relu(rs1*d + ng1*G + EB)
            float v00 = fmaxf(fmaf(rs1A, d[nb0][0], fmaf(ng1A, G0.x, E0.x)), 0.f);
            float v01 = fmaxf(fmaf(rs1A, d[nb0][1], fmaf(ng1A, G0.y, E0.y)), 0.f);
            float v10 = fmaxf(fmaf(rs1B, d[nb0][2], fmaf(ng1B, G0.x, E0.x)), 0.f);
            float v11 = fmaxf(fmaf(rs1B, d[nb0][3], fmaf(ng1B, G0.y, E0.y)), 0.f);
            float v20 = fmaxf(fmaf(rs1A, d[nb1][0], fmaf(ng1A, G1.x, E1.x)), 0.f);
            float v21 = fmaxf(fmaf(rs1A, d[nb1][1], fmaf(ng1A, G1.y, E1.y)), 0.f);
            float v30 = fmaxf(fmaf(rs1B, d[nb1][2], fmaf(ng1B, G1.x, E1.x)), 0.f);
            float v31 = fmaxf(fmaf(rs1B, d[nb1][3], fmaf(ng1B, G1.y, E1.y)), 0.f);
            sg += (v00 + v01) + (v20 + v21);
            qg = fmaf(v00, v00, fmaf(v01, v01, fmaf(v20, v20, fmaf(v21, v21, qg))));
            sh += (v10 + v11) + (v30 + v31);
            qh = fmaf(v10, v10, fmaf(v11, v11, fmaf(v30, v30, fmaf(v31, v31, qh))));
            unsigned av[4];
            av[0] = pack_h2(v00, v01);
            av[1] = pack_h2(v10, v11);
            av[2] = pack_h2(v20, v21);
            av[3] = pack_h2(v30, v31);
            uint4 bd = sm.bDp[kb2][lane];
            mma_f16(ddd, av, bd.x, bd.y);   // v * A3hi
            mma_f16(ddd, av, bd.z, bd.w);   // v * A3lo
        }
        #pragma unroll
        for (int o = 1; o <= 2; o <<= 1) {
            sg += __shfl_xor_sync(0xffffffffu, sg, o);
            qg += __shfl_xor_sync(0xffffffffu, qg, o);
            sh += __shfl_xor_sync(0xffffffffu, sh, o);
            qh += __shfl_xor_sync(0xffffffffu, qh, o);
        }
        float muA = sg * (1.f / 64.f);
        float rsA = rsqrtf(fmaxf(qg * (1.f / 64.f) - muA * muA, 0.f) + 1e-5f);
        float muB = sh * (1.f / 64.f);
        float rsB = rsqrtf(fmaxf(qh * (1.f / 64.f) - muB * muB, 0.f) + 1e-5f);

        // fold LN2 and write directly: out = (S - mu*K2)*rs*bs + C0
        {
            const int pw = it * TILE;
            float* oA = out + outbase + (size_t)(2 * t) * (NG * NP) + pw;
            float* oB = out + outbase + (size_t)(2 * t + 1) * (NG * NP) + pw;
            float m1 = rsA * bsa, m2 = rsA * bsb;
            float m3 = rsB * bsa, m4 = rsB * bsb;
            oA[gg]     = fmaf(ddd[0], m1, fmaf(-muA * m1, K2a, C0a));
            oB[gg]     = fmaf(ddd[1], m2, fmaf(-muA * m2, K2b, C0b));
            oA[gg + 8] = fmaf(ddd[2], m3, fmaf(-muB * m3, K2a, C0a));
            oB[gg + 8] = fmaf(ddd[3], m4, fmaf(-muB * m4, K2b, C0b));
        }
    }
}

extern "C" void kernel_launch(void* const* d_in, const int* in_sizes, int n_in,
                              void* d_out, int out_size) {
    // metadata order: grasp_tokens, scene_points, grasp_poses, W1, b1, g1, beta1,
    //                 W2, b2, g2, beta2, W3, b3, bias_scale
    const float* scene  = (const float*)d_in[1];
    const float* poses  = (const float*)d_in[2];
    const float* W1     = (const float*)d_in[3];
    const float* b1     = (const float*)d_in[4];
    const float* g1     = (const float*)d_in[5];
    const float* be1    = (const float*)d_in[6];
    const float* W2     = (const float*)d_in[7];
    const float* b2     = (const float*)d_in[8];
    const float* g2     = (const float*)d_in[9];
    const float* be2    = (const float*)d_in[10];
    const float* W3     = (const float*)d_in[11];
    const float* b3     = (const float*)d_in[12];
    const float* bscale = (const float*)d_in[13];
    float* out = (float*)d_out;

    cudaFuncSetAttribute(gab_kernel, cudaFuncAttributeMaxDynamicSharedMemorySize,
                         (int)sizeof(Smem));
    dim3 grid(NP / PCHUNK, NG / 8, BATCH);
    gab_kernel<<<grid, 256, sizeof(Smem)>>>(scene, poses, W1, b1, g1, be1,
                                            W2, b2, g2, be2, W3, b3, bscale, out);
}

// round 11
// speedup vs baseline: 1.0991x; 1.0991x over previous
#include <cuda_runtime.h>
#include <cuda_fp16.h>
#include <cstdint>

// Problem dims (fixed by setup_inputs)
#define BATCH 4
#define NG 64
#define NH 8
#define NP 4096
#define PCHUNK 256
#define TILE 16

struct __align__(16) Smem {
    uint4  Bp[8][4][32];      // W2' frags, nb-paired {n0.x,n0.y,n1.x,n1.y}  16 KB
    uint4  W1p[8][32];        // W1' frags, nb-paired {h0,l0,h1,l1}           4 KB
    float4 sp[PCHUNK];        // scene points                                 4 KB
    float  Gs[64];            // G[n]  = g1^T W2[:,n]                        256 B
    float  EBs[64];           // EB[n] = be1^T W2[:,n] + b2[n]               256 B
};                             // ~24.5 KB total

// fp16 split: hi + residual lo, packed fp16x2 (x0 low).
__device__ __forceinline__ void split2h(float x0, float x1, unsigned& hi, unsigned& lo) {
    asm("cvt.rn.f16x2.f32 %0, %1, %2;" : "=r"(hi) : "f"(x1), "f"(x0));
    __half2 hv = *reinterpret_cast<__half2*>(&hi);
    float2 back = __half22float2(hv);
    asm("cvt.rn.f16x2.f32 %0, %1, %2;" : "=r"(lo) : "f"(x1 - back.y), "f"(x0 - back.x));
}
__device__ __forceinline__ unsigned pack_h2(float x0, float x1) {
    unsigned u;
    asm("cvt.rn.f16x2.f32 %0, %1, %2;" : "=r"(u) : "f"(x1), "f"(x0));
    return u;
}
__device__ __forceinline__ float2 unpack_h2(unsigned u) {
    return __half22float2(*reinterpret_cast<__half2*>(&u));
}
__device__ __forceinline__ void mma_f16(float d[4], const unsigned a[4],
                                        unsigned b0, unsigned b1) {
    asm volatile(
        "mma.sync.aligned.m16n8k16.row.col.f32.f16.f16.f32 "
        "{%0,%1,%2,%3},{%4,%5,%6,%7},{%8,%9},{%0,%1,%2,%3};"
        : "+f"(d[0]), "+f"(d[1]), "+f"(d[2]), "+f"(d[3])
        : "r"(a[0]), "r"(a[1]), "r"(a[2]), "r"(a[3]), "r"(b0), "r"(b1));
}
__device__ __forceinline__ void mma_f16_k8(float d[4], unsigned a0, unsigned a1,
                                           unsigned b0) {
    asm volatile(
        "mma.sync.aligned.m16n8k8.row.col.f32.f16.f16.f32 "
        "{%0,%1,%2,%3},{%4,%5},{%6},{%0,%1,%2,%3};"
        : "+f"(d[0]), "+f"(d[1]), "+f"(d[2]), "+f"(d[3])
        : "r"(a0), "r"(a1), "r"(b0));
}

__global__ void __launch_bounds__(256, 2)
gab_kernel(const float* __restrict__ scene,   // (B, NP, 3)
           const float* __restrict__ poses,   // (B, NG, 7)
           const float* __restrict__ W1, const float* __restrict__ b1,
           const float* __restrict__ g1, const float* __restrict__ be1,
           const float* __restrict__ W2, const float* __restrict__ b2,
           const float* __restrict__ g2, const float* __restrict__ be2,
           const float* __restrict__ W3, const float* __restrict__ b3,
           const float* __restrict__ bscale,
           float* __restrict__ out)            // (B, NH, NG, NP)
{
    extern __shared__ __align__(16) char smraw[];
    Smem& sm = *reinterpret_cast<Smem*>(smraw);

    const int tid = threadIdx.x;
    const int b = blockIdx.z;
    const int gbase = blockIdx.y * 8;
    const int p0 = blockIdx.x * PCHUNK;

    // ---- Prologue: W2' frags (nb-paired), W1' frags (nb-paired), G/EB, scene ----
    for (int idx = tid; idx < 8 * 4 * 32; idx += 256) {
        int kb = idx >> 7, rem = idx & 127;
        int nbp = rem >> 5, ln = rem & 31;
        int tt = ln & 3, c = ln >> 2;
        int n0 = (2 * nbp) * 8 + c, n1 = (2 * nbp + 1) * 8 + c;
        int k0 = kb * 16 + 2 * tt;
        float g0 = g1[k0 + 0], g1v = g1[k0 + 1], g8 = g1[k0 + 8], g9 = g1[k0 + 9];
        unsigned x = pack_h2(g0 * W2[(k0 + 0) * 64 + n0], g1v * W2[(k0 + 1) * 64 + n0]);
        unsigned y = pack_h2(g8 * W2[(k0 + 8) * 64 + n0], g9 * W2[(k0 + 9) * 64 + n0]);
        unsigned z = pack_h2(g0 * W2[(k0 + 0) * 64 + n1], g1v * W2[(k0 + 1) * 64 + n1]);
        unsigned w = pack_h2(g8 * W2[(k0 + 8) * 64 + n1], g9 * W2[(k0 + 9) * 64 + n1]);
        sm.Bp[kb][nbp][ln] = make_uint4(x, y, z, w);
    }
    for (int idx = tid; idx < 8 * 32; idx += 256) {
        int kbp = idx >> 5, ln = idx & 31;
        int tt = ln & 3, c = ln >> 2;
        int k0 = 2 * tt, k1 = 2 * tt + 1;
        int n0 = (2 * kbp) * 8 + c, n1 = (2 * kbp + 1) * 8 + c;
        // W1' rows: 0-3 = W1, 4 = b1, 5-7 = 0
        float w00 = (k0 < 4) ? W1[k0 * 128 + n0] : (k0 == 4 ? b1[n0] : 0.f);
        float w01 = (k1 < 4) ? W1[k1 * 128 + n0] : (k1 == 4 ? b1[n0] : 0.f);
        float w10 = (k0 < 4) ? W1[k0 * 128 + n1] : (k0 == 4 ? b1[n1] : 0.f);
        float w11 = (k1 < 4) ? W1[k1 * 128 + n1] : (k1 == 4 ? b1[n1] : 0.f);
        unsigned h0, l0, h1, l1;
        split2h(w00, w01, h0, l0);
        split2h(w10, w11, h1, l1);
        sm.W1p[kbp][ln] = make_uint4(h0, l0, h1, l1);
    }
    if (tid < 64) {
        float G = 0.f, E = 0.f;
        #pragma unroll 8
        for (int k = 0; k < 128; ++k) {
            float w = W2[k * 64 + tid];
            G = fmaf(g1[k], w, G);
            E = fmaf(be1[k], w, E);
        }
        sm.Gs[tid] = G;
        sm.EBs[tid] = E + b2[tid];
    }
    if (tid < PCHUNK) {
        const float* spp = scene + ((size_t)b * NP + p0 + tid) * 3;
        sm.sp[tid] = make_float4(spp[0], spp[1], spp[2], 0.f);
    }
    __syncthreads();

    const int wid = tid >> 5, lane = tid & 31;
    const int g = gbase + wid;
    const int t = lane & 3, gg = lane >> 2;   // mma fragment coords

    // ---- G/EB register cache (fp16x2 per nb, cols 2t,2t+1) ----
    unsigned Greg[8], EBreg[8];
    #pragma unroll
    for (int nb = 0; nb < 8; ++nb) {
        Greg[nb]  = pack_h2(sm.Gs[nb * 8 + 2 * t],  sm.Gs[nb * 8 + 2 * t + 1]);
        EBreg[nb] = pack_h2(sm.EBs[nb * 8 + 2 * t], sm.EBs[nb * 8 + 2 * t + 1]);
    }

    // ---- Stage-D B-fragments: A3 = g2 (*) W3, 2-term fp16, n = gg ----
    unsigned bDh0[4], bDh1[4], bDl0[4], bDl1[4];
    #pragma unroll
    for (int kb2 = 0; kb2 < 4; ++kb2) {
        int k0 = kb2 * 16 + 2 * t;
        float a0 = __ldg(g2 + k0 + 0) * __ldg(W3 + (k0 + 0) * 8 + gg);
        float a1 = __ldg(g2 + k0 + 1) * __ldg(W3 + (k0 + 1) * 8 + gg);
        float a2 = __ldg(g2 + k0 + 8) * __ldg(W3 + (k0 + 8) * 8 + gg);
        float a3 = __ldg(g2 + k0 + 9) * __ldg(W3 + (k0 + 9) * 8 + gg);
        split2h(a0, a1, bDh0[kb2], bDl0[kb2]);
        split2h(a2, a3, bDh1[kb2], bDl1[kb2]);
    }

    // ---- Per-head fold constants for heads h0 = 2t, h1 = 2t+1 ----
    float K2a = 0.f, K2b = 0.f, K1a = 0.f, K1b = 0.f;
    #pragma unroll 8
    for (int c = 0; c < 64; ++c) {
        float2 w = *reinterpret_cast<const float2*>(W3 + c * 8 + 2 * t);
        float gc = __ldg(g2 + c), bc = __ldg(be2 + c);
        K2a = fmaf(gc, w.x, K2a); K2b = fmaf(gc, w.y, K2b);
        K1a = fmaf(bc, w.x, K1a); K1b = fmaf(bc, w.y, K1b);
    }
    const float bsa = __ldg(bscale + 2 * t), bsb = __ldg(bscale + 2 * t + 1);
    const float C0a = (K1a + __ldg(b3 + 2 * t)) * bsa;
    const float C0b = (K1b + __ldg(b3 + 2 * t + 1)) * bsb;

    // Per-warp pose -> rotation
    const float* pp = poses + ((size_t)(b * NG + g)) * 7;
    float tx = pp[0], ty = pp[1], tz = pp[2];
    float qx = pp[3], qy = pp[4], qz = pp[5], qw = pp[6];
    float inv = 1.f / (sqrtf(qx * qx + qy * qy + qz * qz + qw * qw) + 1e-8f);
    qx *= inv; qy *= inv; qz *= inv; qw *= inv;
    float xx = qx * qx, yy = qy * qy, zz = qz * qz;
    float xy = qx * qy, xz = qx * qz, yz = qy * qz;
    float wx = qw * qx, wy = qw * qy, wz = qw * qz;
    float R00 = 1.f - 2.f * (yy + zz), R01 = 2.f * (xy - wz), R02 = 2.f * (xz + wy);
    float R10 = 2.f * (xy + wz), R11 = 1.f - 2.f * (xx + zz), R12 = 2.f * (yz - wx);
    float R20 = 2.f * (xz - wy), R21 = 2.f * (yz + wx), R22 = 1.f - 2.f * (xx + yy);

    const size_t outbase = (((size_t)b * NH) * NG + g) * NP + p0;

    for (int it = 0; it < PCHUNK / TILE; ++it) {
        // ---- Geometry for this lane's two rows (gg, gg+8) ----
        float4 PA = sm.sp[it * TILE + gg];
        float4 PB = sm.sp[it * TILE + gg + 8];
        float rxA = PA.x - tx, ryA = PA.y - ty, rzA = PA.z - tz;
        float lxA = R00 * rxA + R10 * ryA + R20 * rzA;
        float lyA = R01 * rxA + R11 * ryA + R21 * rzA;
        float lzA = R02 * rxA + R12 * ryA + R22 * rzA;
        float ddA = sqrtf(lxA * lxA + lyA * lyA + lzA * lzA);
        float rxB = PB.x - tx, ryB = PB.y - ty, rzB = PB.z - tz;
        float lxB = R00 * rxB + R10 * ryB + R20 * rzB;
        float lyB = R01 * rxB + R11 * ryB + R21 * rzB;
        float lzB = R02 * rxB + R12 * ryB + R22 * rzB;
        float ddB = sqrtf(lxB * lxB + lyB * lyB + lzB * lzB);
        // A-frag (m16n8k8): k cols 2t,2t+1 of feats = (lx,ly,lz,dd,1,0,0,0)
        float s0A = (t == 0) ? lxA : (t == 1) ? lzA : (t == 2) ? 1.f : 0.f;
        float s1A = (t == 0) ? lyA : (t == 1) ? ddA : 0.f;
        float s0B = (t == 0) ? lxB : (t == 1) ? lzB : (t == 2) ? 1.f : 0.f;
        float s1B = (t == 0) ? lyB : (t == 1) ? ddB : 0.f;
        unsigned af0 = pack_h2(s0A, s1A);
        unsigned af1 = pack_h2(s0B, s1B);

        // ---- Stage B: a = relu(feats @ W1') via 16x m16n8k8 (2-term W1), wide loads ----
        unsigned afr[8][4];
        float sA = 0.f, qA = 0.f, sB = 0.f, qB = 0.f;
        #pragma unroll
        for (int kbp = 0; kbp < 8; ++kbp) {
            uint4 wb = sm.W1p[kbp][lane];
            float d0[4] = {0.f, 0.f, 0.f, 0.f};
            float d1[4] = {0.f, 0.f, 0.f, 0.f};
            mma_f16_k8(d0, af0, af1, wb.x);
            mma_f16_k8(d0, af0, af1, wb.y);
            mma_f16_k8(d1, af0, af1, wb.z);
            mma_f16_k8(d1, af0, af1, wb.w);
            float v0 = fmaxf(d0[0], 0.f), v1 = fmaxf(d0[1], 0.f);
            float v2 = fmaxf(d0[2], 0.f), v3 = fmaxf(d0[3], 0.f);
            float v4 = fmaxf(d1[0], 0.f), v5 = fmaxf(d1[1], 0.f);
            float v6 = fmaxf(d1[2], 0.f), v7 = fmaxf(d1[3], 0.f);
            sA += (v0 + v1) + (v4 + v5);
            qA = fmaf(v0, v0, fmaf(v1, v1, fmaf(v4, v4, fmaf(v5, v5, qA))));
            sB += (v2 + v3) + (v6 + v7);
            qB = fmaf(v2, v2, fmaf(v3, v3, fmaf(v6, v6, fmaf(v7, v7, qB))));
            afr[kbp][0] = pack_h2(v0, v1);
            afr[kbp][1] = pack_h2(v2, v3);
            afr[kbp][2] = pack_h2(v4, v5);
            afr[kbp][3] = pack_h2(v6, v7);
        }
        // LN1 stats over 128 cols: reduce across t-quad
        #pragma unroll
        for (int o = 1; o <= 2; o <<= 1) {
            sA += __shfl_xor_sync(0xffffffffu, sA, o);
            qA += __shfl_xor_sync(0xffffffffu, qA, o);
            sB += __shfl_xor_sync(0xffffffffu, sB, o);
            qB += __shfl_xor_sync(0xffffffffu, qB, o);
        }
        float mu1A = sA * (1.f / 128.f);
        float rs1A = rsqrtf(fmaxf(qA * (1.f / 128.f) - mu1A * mu1A, 0.f) + 1e-5f);
        float ng1A = -mu1A * rs1A;
        float mu1B = sB * (1.f / 128.f);
        float rs1B = rsqrtf(fmaxf(qB * (1.f / 128.f) - mu1B * mu1B, 0.f) + 1e-5f);
        float ng1B = -mu1B * rs1B;

        // ---- Stage C: a16 @ W2' (single fp16 both sides), wide B loads ----
        float d[8][4];
        #pragma unroll
        for (int nb = 0; nb < 8; ++nb) { d[nb][0] = d[nb][1] = d[nb][2] = d[nb][3] = 0.f; }
        #pragma unroll
        for (int kb = 0; kb < 8; ++kb) {
            #pragma unroll
            for (int nbp = 0; nbp < 4; ++nbp) {
                uint4 bp = sm.Bp[kb][nbp][lane];
                mma_f16(d[2 * nbp],     afr[kb], bp.x, bp.y);
                mma_f16(d[2 * nbp + 1], afr[kb], bp.z, bp.w);
            }
        }

        // ---- Epilogue (LN1-fold) + Stage D chaining ----
        float ddd[4] = {0.f, 0.f, 0.f, 0.f};
        float sg = 0.f, qg = 0.f, sh = 0.f, qh = 0.f;
        #pragma unroll
        for (int kb2 = 0; kb2 < 4; ++kb2) {
            const int nb0 = 2 * kb2, nb1 = 2 * kb2 + 1;
            float2 G0 = unpack_h2(Greg[nb0]), E0 = unpack_h2(EBreg[nb0]);
            float2 G1 = unpack_h2(Greg[nb1]), E1 = unpack_h2(EBreg[nb1]);
            // v = relu(rs1*d + ng1*G + EB)
            float v00 = fmaxf(fmaf(rs1A, d[nb0][0], fmaf(ng1A, G0.x, E0.x)), 0.f);
            float v01 = fmaxf(fmaf(rs1A, d[nb0][1], fmaf(ng1A, G0.y, E0.y)), 0.f);
            float v10 = fmaxf(fmaf(rs1B, d[nb0][2], fmaf(ng1B, G0.x, E0.x)), 0.f);
            float v11 = fmaxf(fmaf(rs1B, d[nb0][3], fmaf(ng1B, G0.y, E0.y)), 0.f);
            float v20 = fmaxf(fmaf(rs1A, d[nb1][0], fmaf(ng1A, G1.x, E1.x)), 0.f);
            float v21 = fmaxf(fmaf(rs1A, d[nb1][1], fmaf(ng1A, G1.y, E1.y)), 0.f);
            float v30 = fmaxf(fmaf(rs1B, d[nb1][2], fmaf(ng1B, G1.x, E1.x)), 0.f);
            float v31 = fmaxf(fmaf(rs1B, d[nb1][3], fmaf(ng1B, G1.y, E1.y)), 0.f);
            sg += (v00 + v01) + (v20 + v21);
            qg = fmaf(v00, v00, fmaf(v01, v01, fmaf(v20, v20, fmaf(v21, v21, qg))));
            sh += (v10 + v11) + (v30 + v31);
            qh = fmaf(v10, v10, fmaf(v11, v11, fmaf(v30, v30, fmaf(v31, v31, qh))));
            unsigned av[4];
            av[0] = pack_h2(v00, v01);
            av[1] = pack_h2(v10, v11);
            av[2] = pack_h2(v20, v21);
            av[3] = pack_h2(v30, v31);
            mma_f16(ddd, av, bDh0[kb2], bDh1[kb2]);   // v * A3hi
            mma_f16(ddd, av, bDl0[kb2], bDl1[kb2]);   // v * A3lo
        }
        #pragma unroll
        for (int o = 1; o <= 2; o <<= 1) {
            sg += __shfl_xor_sync(0xffffffffu, sg, o);
            qg += __shfl_xor_sync(0xffffffffu, qg, o);
            sh += __shfl_xor_sync(0xffffffffu, sh, o);
            qh += __shfl_xor_sync(0xffffffffu, qh, o);
        }
        float muA = sg * (1.f / 64.f);
        float rsA = rsqrtf(fmaxf(qg * (1.f / 64.f) - muA * muA, 0.f) + 1e-5f);
        float muB = sh * (1.f / 64.f);
        float rsB = rsqrtf(fmaxf(qh * (1.f / 64.f) - muB * muB, 0.f) + 1e-5f);

        // fold LN2 and write directly: out = (S - mu*K2)*rs*bs + C0
        {
            const int pw = it * TILE;
            float* oA = out + outbase + (size_t)(2 * t) * (NG * NP) + pw;
            float* oB = out + outbase + (size_t)(2 * t + 1) * (NG * NP) + pw;
            float m1 = rsA * bsa, m2 = rsA * bsb;
            float m3 = rsB * bsa, m4 = rsB * bsb;
            oA[gg]     = fmaf(ddd[0], m1, fmaf(-muA * m1, K2a, C0a));
            oB[gg]     = fmaf(ddd[1], m2, fmaf(-muA * m2, K2b, C0b));
            oA[gg + 8] = fmaf(ddd[2], m3, fmaf(-muB * m3, K2a, C0a));
            oB[gg + 8] = fmaf(ddd[3], m4, fmaf(-muB * m4, K2b, C0b));
        }
    }
}

extern "C" void kernel_launch(void* const* d_in, const int* in_sizes, int n_in,
                              void* d_out, int out_size) {
    // metadata order: grasp_tokens, scene_points, grasp_poses, W1, b1, g1, beta1,
    //                 W2, b2, g2, beta2, W3, b3, bias_scale
    const float* scene  = (const float*)d_in[1];
    const float* poses  = (const float*)d_in[2];
    const float* W1     = (const float*)d_in[3];
    const float* b1     = (const float*)d_in[4];
    const float* g1     = (const float*)d_in[5];
    const float* be1    = (const float*)d_in[6];
    const float* W2     = (const float*)d_in[7];
    const float* b2     = (const float*)d_in[8];
    const float* g2     = (const float*)d_in[9];
    const float* be2    = (const float*)d_in[10];
    const float* W3     = (const float*)d_in[11];
    const float* b3     = (const float*)d_in[12];
    const float* bscale = (const float*)d_in[13];
    float* out = (float*)d_out;

    cudaFuncSetAttribute(gab_kernel, cudaFuncAttributeMaxDynamicSharedMemorySize,
                         (int)sizeof(Smem));
    dim3 grid(NP / PCHUNK, NG / 8, BATCH);
    gab_kernel<<<grid, 256, sizeof(Smem)>>>(scene, poses, W1, b1, g1, be1,
                                            W2, b2, g2, be2, W3, b3, bscale, out);
}

// round 12
// speedup vs baseline: 1.2225x; 1.1123x over previous
#include <cuda_runtime.h>
#include <cuda_fp16.h>
#include <cstdint>

// Problem dims (fixed by setup_inputs)
#define BATCH 4
#define NG 64
#define NH 8
#define NP 4096
#define TILE 16
#define PITEM 64              // points per work item (4 tiles)
#define NITEMS 2048           // 4 b * 8 gchunks * 64 pchunks
#define PBLKS 296             // 148 SMs * 2 blocks -> one full wave

struct __align__(16) Smem {
    uint4  Bp[8][4][32];      // W2' frags, nb-paired {n0.x,n0.y,n1.x,n1.y}  16 KB
    uint4  W1p[8][32];        // W1' frags, nb-paired {h0,l0,h1,l1}           4 KB
    float4 sp[2][PITEM];      // scene points, double-buffered               2 KB
    float  Gs[64];            // G[n]  = g1^T W2[:,n]                       256 B
    float  EBs[64];           // EB[n] = be1^T W2[:,n] + b2[n]              256 B
};                             // ~22.5 KB total

// fp16 split: hi + residual lo, packed fp16x2 (x0 low).
__device__ __forceinline__ void split2h(float x0, float x1, unsigned& hi, unsigned& lo) {
    asm("cvt.rn.f16x2.f32 %0, %1, %2;" : "=r"(hi) : "f"(x1), "f"(x0));
    __half2 hv = *reinterpret_cast<__half2*>(&hi);
    float2 back = __half22float2(hv);
    asm("cvt.rn.f16x2.f32 %0, %1, %2;" : "=r"(lo) : "f"(x1 - back.y), "f"(x0 - back.x));
}
__device__ __forceinline__ unsigned pack_h2(float x0, float x1) {
    unsigned u;
    asm("cvt.rn.f16x2.f32 %0, %1, %2;" : "=r"(u) : "f"(x1), "f"(x0));
    return u;
}
__device__ __forceinline__ float2 unpack_h2(unsigned u) {
    return __half22float2(*reinterpret_cast<__half2*>(&u));
}
__device__ __forceinline__ void mma_f16(float d[4], const unsigned a[4],
                                        unsigned b0, unsigned b1) {
    asm volatile(
        "mma.sync.aligned.m16n8k16.row.col.f32.f16.f16.f32 "
        "{%0,%1,%2,%3},{%4,%5,%6,%7},{%8,%9},{%0,%1,%2,%3};"
        : "+f"(d[0]), "+f"(d[1]), "+f"(d[2]), "+f"(d[3])
        : "r"(a[0]), "r"(a[1]), "r"(a[2]), "r"(a[3]), "r"(b0), "r"(b1));
}
__device__ __forceinline__ void mma_f16_k8(float d[4], unsigned a0, unsigned a1,
                                           unsigned b0) {
    asm volatile(
        "mma.sync.aligned.m16n8k8.row.col.f32.f16.f16.f32 "
        "{%0,%1,%2,%3},{%4,%5},{%6},{%0,%1,%2,%3};"
        : "+f"(d[0]), "+f"(d[1]), "+f"(d[2]), "+f"(d[3])
        : "r"(a0), "r"(a1), "r"(b0));
}

__global__ void __launch_bounds__(256, 2)
gab_kernel(const float* __restrict__ scene,   // (B, NP, 3)
           const float* __restrict__ poses,   // (B, NG, 7)
           const float* __restrict__ W1, const float* __restrict__ b1,
           const float* __restrict__ g1, const float* __restrict__ be1,
           const float* __restrict__ W2, const float* __restrict__ b2,
           const float* __restrict__ g2, const float* __restrict__ be2,
           const float* __restrict__ W3, const float* __restrict__ b3,
           const float* __restrict__ bscale,
           float* __restrict__ out)            // (B, NH, NG, NP)
{
    extern __shared__ __align__(16) char smraw[];
    Smem& sm = *reinterpret_cast<Smem*>(smraw);

    const int tid = threadIdx.x;

    // ---- Once-per-block prologue (all g-independent) ----
    for (int idx = tid; idx < 8 * 4 * 32; idx += 256) {
        int kb = idx >> 7, rem = idx & 127;
        int nbp = rem >> 5, ln = rem & 31;
        int tt = ln & 3, c = ln >> 2;
        int n0 = (2 * nbp) * 8 + c, n1 = (2 * nbp + 1) * 8 + c;
        int k0 = kb * 16 + 2 * tt;
        float g0 = g1[k0 + 0], g1v = g1[k0 + 1], g8 = g1[k0 + 8], g9 = g1[k0 + 9];
        unsigned x = pack_h2(g0 * W2[(k0 + 0) * 64 + n0], g1v * W2[(k0 + 1) * 64 + n0]);
        unsigned y = pack_h2(g8 * W2[(k0 + 8) * 64 + n0], g9 * W2[(k0 + 9) * 64 + n0]);
        unsigned z = pack_h2(g0 * W2[(k0 + 0) * 64 + n1], g1v * W2[(k0 + 1) * 64 + n1]);
        unsigned w = pack_h2(g8 * W2[(k0 + 8) * 64 + n1], g9 * W2[(k0 + 9) * 64 + n1]);
        sm.Bp[kb][nbp][ln] = make_uint4(x, y, z, w);
    }
    for (int idx = tid; idx < 8 * 32; idx += 256) {
        int kbp = idx >> 5, ln = idx & 31;
        int tt = ln & 3, c = ln >> 2;
        int k0 = 2 * tt, k1 = 2 * tt + 1;
        int n0 = (2 * kbp) * 8 + c, n1 = (2 * kbp + 1) * 8 + c;
        // W1' rows: 0-3 = W1, 4 = b1, 5-7 = 0
        float w00 = (k0 < 4) ? W1[k0 * 128 + n0] : (k0 == 4 ? b1[n0] : 0.f);
        float w01 = (k1 < 4) ? W1[k1 * 128 + n0] : (k1 == 4 ? b1[n0] : 0.f);
        float w10 = (k0 < 4) ? W1[k0 * 128 + n1] : (k0 == 4 ? b1[n1] : 0.f);
        float w11 = (k1 < 4) ? W1[k1 * 128 + n1] : (k1 == 4 ? b1[n1] : 0.f);
        unsigned h0, l0, h1, l1;
        split2h(w00, w01, h0, l0);
        split2h(w10, w11, h1, l1);
        sm.W1p[kbp][ln] = make_uint4(h0, l0, h1, l1);
    }
    if (tid < 64) {
        float G = 0.f, E = 0.f;
        #pragma unroll 8
        for (int k = 0; k < 128; ++k) {
            float w = W2[k * 64 + tid];
            G = fmaf(g1[k], w, G);
            E = fmaf(be1[k], w, E);
        }
        sm.Gs[tid] = G;
        sm.EBs[tid] = E + b2[tid];
    }
    // Stage first item's scene chunk into buffer 0
    {
        int item0 = blockIdx.x;
        if (item0 < NITEMS && tid < PITEM) {
            int bb = item0 >> 9;
            int p0 = (item0 & 63) << 6;
            const float* spp = scene + ((size_t)bb * NP + p0 + tid) * 3;
            sm.sp[0][tid] = make_float4(spp[0], spp[1], spp[2], 0.f);
        }
    }
    __syncthreads();

    const int wid = tid >> 5, lane = tid & 31;
    const int t = lane & 3, gg = lane >> 2;   // mma fragment coords

    // ---- G/EB register cache (fp16x2 per nb, cols 2t,2t+1) ----
    unsigned Greg[8], EBreg[8];
    #pragma unroll
    for (int nb = 0; nb < 8; ++nb) {
        Greg[nb]  = pack_h2(sm.Gs[nb * 8 + 2 * t],  sm.Gs[nb * 8 + 2 * t + 1]);
        EBreg[nb] = pack_h2(sm.EBs[nb * 8 + 2 * t], sm.EBs[nb * 8 + 2 * t + 1]);
    }

    // ---- Stage-D B-fragments: A3 = g2 (*) W3, 2-term fp16, n = gg (g-independent) ----
    unsigned bDh0[4], bDh1[4], bDl0[4], bDl1[4];
    #pragma unroll
    for (int kb2 = 0; kb2 < 4; ++kb2) {
        int k0 = kb2 * 16 + 2 * t;
        float a0 = __ldg(g2 + k0 + 0) * __ldg(W3 + (k0 + 0) * 8 + gg);
        float a1 = __ldg(g2 + k0 + 1) * __ldg(W3 + (k0 + 1) * 8 + gg);
        float a2 = __ldg(g2 + k0 + 8) * __ldg(W3 + (k0 + 8) * 8 + gg);
        float a3 = __ldg(g2 + k0 + 9) * __ldg(W3 + (k0 + 9) * 8 + gg);
        split2h(a0, a1, bDh0[kb2], bDl0[kb2]);
        split2h(a2, a3, bDh1[kb2], bDl1[kb2]);
    }

    // ---- Per-head fold constants for heads h0 = 2t, h1 = 2t+1 (g-independent) ----
    float K2a = 0.f, K2b = 0.f, K1a = 0.f, K1b = 0.f;
    #pragma unroll 8
    for (int c = 0; c < 64; ++c) {
        float2 w = *reinterpret_cast<const float2*>(W3 + c * 8 + 2 * t);
        float gc = __ldg(g2 + c), bc = __ldg(be2 + c);
        K2a = fmaf(gc, w.x, K2a); K2b = fmaf(gc, w.y, K2b);
        K1a = fmaf(bc, w.x, K1a); K1b = fmaf(bc, w.y, K1b);
    }
    const float bsa = __ldg(bscale + 2 * t), bsb = __ldg(bscale + 2 * t + 1);
    const float C0a = (K1a + __ldg(b3 + 2 * t)) * bsa;
    const float C0b = (K1b + __ldg(b3 + 2 * t + 1)) * bsb;

    // ---- Persistent item loop: static stride schedule ----
    int bufn = 0;
    for (int item = blockIdx.x; item < NITEMS; item += PBLKS, bufn ^= 1) {
        __syncthreads();   // sp[bufn] staged & visible; prev readers of sp[bufn^1] done

        // Prefetch next item's scene chunk into the alternate buffer
        int nxt = item + PBLKS;
        if (nxt < NITEMS && tid < PITEM) {
            int bbn = nxt >> 9;
            int p0n = (nxt & 63) << 6;
            const float* spp = scene + ((size_t)bbn * NP + p0n + tid) * 3;
            sm.sp[bufn ^ 1][tid] = make_float4(spp[0], spp[1], spp[2], 0.f);
        }

        // Decode item
        const int bb = item >> 9;
        const int rem = item & 511;
        const int g = ((rem >> 6) << 3) + wid;
        const int p0 = (rem & 63) << 6;
        const float4* spb = sm.sp[bufn];

        // Pose -> rotation (per item, per warp)
        const float* pp = poses + ((size_t)(bb * NG + g)) * 7;
        float tx = pp[0], ty = pp[1], tz = pp[2];
        float qx = pp[3], qy = pp[4], qz = pp[5], qw = pp[6];
        float inv = 1.f / (sqrtf(qx * qx + qy * qy + qz * qz + qw * qw) + 1e-8f);
        qx *= inv; qy *= inv; qz *= inv; qw *= inv;
        float xx = qx * qx, yy = qy * qy, zz = qz * qz;
        float xy = qx * qy, xz = qx * qz, yz = qy * qz;
        float wx = qw * qx, wy = qw * qy, wz = qw * qz;
        float R00 = 1.f - 2.f * (yy + zz), R01 = 2.f * (xy - wz), R02 = 2.f * (xz + wy);
        float R10 = 2.f * (xy + wz), R11 = 1.f - 2.f * (xx + zz), R12 = 2.f * (yz - wx);
        float R20 = 2.f * (xz - wy), R21 = 2.f * (yz + wx), R22 = 1.f - 2.f * (xx + yy);

        const size_t outbase = (((size_t)bb * NH) * NG + g) * NP + p0;

        for (int itl = 0; itl < PITEM / TILE; ++itl) {
            // ---- Geometry for this lane's two rows (gg, gg+8) ----
            float4 PA = spb[itl * TILE + gg];
            float4 PB = spb[itl * TILE + gg + 8];
            float rxA = PA.x - tx, ryA = PA.y - ty, rzA = PA.z - tz;
            float lxA = R00 * rxA + R10 * ryA + R20 * rzA;
            float lyA = R01 * rxA + R11 * ryA + R21 * rzA;
            float lzA = R02 * rxA + R12 * ryA + R22 * rzA;
            float ddA = sqrtf(lxA * lxA + lyA * lyA + lzA * lzA);
            float rxB = PB.x - tx, ryB = PB.y - ty, rzB = PB.z - tz;
            float lxB = R00 * rxB + R10 * ryB + R20 * rzB;
            float lyB = R01 * rxB + R11 * ryB + R21 * rzB;
            float lzB = R02 * rxB + R12 * ryB + R22 * rzB;
            float ddB = sqrtf(lxB * lxB + lyB * lyB + lzB * lzB);
            // A-frag (m16n8k8): k cols 2t,2t+1 of feats = (lx,ly,lz,dd,1,0,0,0)
            float s0A = (t == 0) ? lxA : (t == 1) ? lzA : (t == 2) ? 1.f : 0.f;
            float s1A = (t == 0) ? lyA : (t == 1) ? ddA : 0.f;
            float s0B = (t == 0) ? lxB : (t == 1) ? lzB : (t == 2) ? 1.f : 0.f;
            float s1B = (t == 0) ? lyB : (t == 1) ? ddB : 0.f;
            unsigned af0 = pack_h2(s0A, s1A);
            unsigned af1 = pack_h2(s0B, s1B);

            // ---- Stage B: a = relu(feats @ W1') via 16x m16n8k8 (2-term W1) ----
            unsigned afr[8][4];
            float sA = 0.f, qA = 0.f, sB = 0.f, qB = 0.f;
            #pragma unroll
            for (int kbp = 0; kbp < 8; ++kbp) {
                uint4 wb = sm.W1p[kbp][lane];
                float d0[4] = {0.f, 0.f, 0.f, 0.f};
                float d1[4] = {0.f, 0.f, 0.f, 0.f};
                mma_f16_k8(d0, af0, af1, wb.x);
                mma_f16_k8(d0, af0, af1, wb.y);
                mma_f16_k8(d1, af0, af1, wb.z);
                mma_f16_k8(d1, af0, af1, wb.w);
                float v0 = fmaxf(d0[0], 0.f), v1 = fmaxf(d0[1], 0.f);
                float v2 = fmaxf(d0[2], 0.f), v3 = fmaxf(d0[3], 0.f);
                float v4 = fmaxf(d1[0], 0.f), v5 = fmaxf(d1[1], 0.f);
                float v6 = fmaxf(d1[2], 0.f), v7 = fmaxf(d1[3], 0.f);
                sA += (v0 + v1) + (v4 + v5);
                qA = fmaf(v0, v0, fmaf(v1, v1, fmaf(v4, v4, fmaf(v5, v5, qA))));
                sB += (v2 + v3) + (v6 + v7);
                qB = fmaf(v2, v2, fmaf(v3, v3, fmaf(v6, v6, fmaf(v7, v7, qB))));
                afr[kbp][0] = pack_h2(v0, v1);
                afr[kbp][1] = pack_h2(v2, v3);
                afr[kbp][2] = pack_h2(v4, v5);
                afr[kbp][3] = pack_h2(v6, v7);
            }
            // LN1 stats over 128 cols: reduce across t-quad
            #pragma unroll
            for (int o = 1; o <= 2; o <<= 1) {
                sA += __shfl_xor_sync(0xffffffffu, sA, o);
                qA += __shfl_xor_sync(0xffffffffu, qA, o);
                sB += __shfl_xor_sync(0xffffffffu, sB, o);
                qB += __shfl_xor_sync(0xffffffffu, qB, o);
            }
            float mu1A = sA * (1.f / 128.f);
            float rs1A = rsqrtf(fmaxf(qA * (1.f / 128.f) - mu1A * mu1A, 0.f) + 1e-5f);
            float ng1A = -mu1A * rs1A;
            float mu1B = sB * (1.f / 128.f);
            float rs1B = rsqrtf(fmaxf(qB * (1.f / 128.f) - mu1B * mu1B, 0.f) + 1e-5f);
            float ng1B = -mu1B * rs1B;

            // ---- Stage C: a16 @ W2' (single fp16 both sides), wide B loads ----
            float d[8][4];
            #pragma unroll
            for (int nb = 0; nb < 8; ++nb) { d[nb][0] = d[nb][1] = d[nb][2] = d[nb][3] = 0.f; }
            #pragma unroll
            for (int kb = 0; kb < 8; ++kb) {
                #pragma unroll
                for (int nbp = 0; nbp < 4; ++nbp) {
                    uint4 bp = sm.Bp[kb][nbp][lane];
                    mma_f16(d[2 * nbp],     afr[kb], bp.x, bp.y);
                    mma_f16(d[2 * nbp + 1], afr[kb], bp.z, bp.w);
                }
            }

            // ---- Epilogue (LN1-fold) + Stage D chaining ----
            float ddd[4] = {0.f, 0.f, 0.f, 0.f};
            float sg = 0.f, qg = 0.f, sh = 0.f, qh = 0.f;
            #pragma unroll
            for (int kb2 = 0; kb2 < 4; ++kb2) {
                const int nb0 = 2 * kb2, nb1 = 2 * kb2 + 1;
                float2 G0 = unpack_h2(Greg[nb0]), E0 = unpack_h2(EBreg[nb0]);
                float2 G1 = unpack_h2(Greg[nb1]), E1 = unpack_h2(EBreg[nb1]);
                // v = relu(rs1*d + ng1*G + EB)
                float v00 = fmaxf(fmaf(rs1A, d[nb0][0], fmaf(ng1A, G0.x, E0.x)), 0.f);
                float v01 = fmaxf(fmaf(rs1A, d[nb0][1], fmaf(ng1A, G0.y, E0.y)), 0.f);
                float v10 = fmaxf(fmaf(rs1B, d[nb0][2], fmaf(ng1B, G0.x, E0.x)), 0.f);
                float v11 = fmaxf(fmaf(rs1B, d[nb0][3], fmaf(ng1B, G0.y, E0.y)), 0.f);
                float v20 = fmaxf(fmaf(rs1A, d[nb1][0], fmaf(ng1A, G1.x, E1.x)), 0.f);
                float v21 = fmaxf(fmaf(rs1A, d[nb1][1], fmaf(ng1A, G1.y, E1.y)), 0.f);
                float v30 = fmaxf(fmaf(rs1B, d[nb1][2], fmaf(ng1B, G1.x, E1.x)), 0.f);
                float v31 = fmaxf(fmaf(rs1B, d[nb1][3], fmaf(ng1B, G1.y, E1.y)), 0.f);
                sg += (v00 + v01) + (v20 + v21);
                qg = fmaf(v00, v00, fmaf(v01, v01, fmaf(v20, v20, fmaf(v21, v21, qg))));
                sh += (v10 + v11) + (v30 + v31);
                qh = fmaf(v10, v10, fmaf(v11, v11, fmaf(v30, v30, fmaf(v31, v31, qh))));
                unsigned av[4];
                av[0] = pack_h2(v00, v01);
                av[1] = pack_h2(v10, v11);
                av[2] = pack_h2(v20, v21);
                av[3] = pack_h2(v30, v31);
                mma_f16(ddd, av, bDh0[kb2], bDh1[kb2]);   // v * A3hi
                mma_f16(ddd, av, bDl0[kb2], bDl1[kb2]);   // v * A3lo
            }
            #pragma unroll
            for (int o = 1; o <= 2; o <<= 1) {
                sg += __shfl_xor_sync(0xffffffffu, sg, o);
                qg += __shfl_xor_sync(0xffffffffu, qg, o);
                sh += __shfl_xor_sync(0xffffffffu, sh, o);
                qh += __shfl_xor_sync(0xffffffffu, qh, o);
            }
            float muA = sg * (1.f / 64.f);
            float rsA = rsqrtf(fmaxf(qg * (1.f / 64.f) - muA * muA, 0.f) + 1e-5f);
            float muB = sh * (1.f / 64.f);
            float rsB = rsqrtf(fmaxf(qh * (1.f / 64.f) - muB * muB, 0.f) + 1e-5f);

            // fold LN2 and write directly: out = (S - mu*K2)*rs*bs + C0
            {
                const int pw = itl * TILE;
                float* oA = out + outbase + (size_t)(2 * t) * (NG * NP) + pw;
                float* oB = out + outbase + (size_t)(2 * t + 1) * (NG * NP) + pw;
                float m1 = rsA * bsa, m2 = rsA * bsb;
                float m3 = rsB * bsa, m4 = rsB * bsb;
                oA[gg]     = fmaf(ddd[0], m1, fmaf(-muA * m1, K2a, C0a));
                oB[gg]     = fmaf(ddd[1], m2, fmaf(-muA * m2, K2b, C0b));
                oA[gg + 8] = fmaf(ddd[2], m3, fmaf(-muB * m3, K2a, C0a));
                oB[gg + 8] = fmaf(ddd[3], m4, fmaf(-muB * m4, K2b, C0b));
            }
        }
    }
}

extern "C" void kernel_launch(void* const* d_in, const int* in_sizes, int n_in,
                              void* d_out, int out_size) {
    // metadata order: grasp_tokens, scene_points, grasp_poses, W1, b1, g1, beta1,
    //                 W2, b2, g2, beta2, W3, b3, bias_scale
    const float* scene  = (const float*)d_in[1];
    const float* poses  = (const float*)d_in[2];
    const float* W1     = (const float*)d_in[3];
    const float* b1     = (const float*)d_in[4];
    const float* g1     = (const float*)d_in[5];
    const float* be1    = (const float*)d_in[6];
    const float* W2     = (const float*)d_in[7];
    const float* b2     = (const float*)d_in[8];
    const float* g2     = (const float*)d_in[9];
    const float* be2    = (const float*)d_in[10];
    const float* W3     = (const float*)d_in[11];
    const float* b3     = (const float*)d_in[12];
    const float* bscale = (const float*)d_in[13];
    float* out = (float*)d_out;

    cudaFuncSetAttribute(gab_kernel, cudaFuncAttributeMaxDynamicSharedMemorySize,
                         (int)sizeof(Smem));
    gab_kernel<<<PBLKS, 256, sizeof(Smem)>>>(scene, poses, W1, b1, g1, be1,
                                             W2, b2, g2, be2, W3, b3, bscale, out);
}

// round 13
// speedup vs baseline: 1.2496x; 1.0222x over previous
#include <cuda_runtime.h>
#include <cuda_fp16.h>
#include <cstdint>

// Problem dims (fixed by setup_inputs)
#define BATCH 4
#define NG 64
#define NH 8
#define NP 4096
#define TILE 16
#define PITEM 64              // points per work item (4 tiles)
#define NITEMS 2048           // 4 b * 8 gchunks * 64 pchunks
#define PBLKS 296             // 148 SMs * 2 blocks -> one full wave

struct __align__(16) Smem {
    uint4  Bp[8][4][32];      // W2' frags, nb-paired {n0.x,n0.y,n1.x,n1.y}  16 KB
    uint4  W1p[8][32];        // W1' frags, nb-paired {h0,l0,h1,l1}           4 KB
    float4 sp[2][PITEM];      // scene points, double-buffered               2 KB
    float  Gs[64];            // G[n]  = g1^T W2[:,n]                       256 B
    float  EBs[64];           // EB[n] = be1^T W2[:,n] + b2[n]              256 B
};                             // ~22.5 KB total

// fp16 split: hi + residual lo, packed fp16x2 (x0 low).
__device__ __forceinline__ void split2h(float x0, float x1, unsigned& hi, unsigned& lo) {
    asm("cvt.rn.f16x2.f32 %0, %1, %2;" : "=r"(hi) : "f"(x1), "f"(x0));
    __half2 hv = *reinterpret_cast<__half2*>(&hi);
    float2 back = __half22float2(hv);
    asm("cvt.rn.f16x2.f32 %0, %1, %2;" : "=r"(lo) : "f"(x1 - back.y), "f"(x0 - back.x));
}
__device__ __forceinline__ unsigned pack_h2(float x0, float x1) {
    unsigned u;
    asm("cvt.rn.f16x2.f32 %0, %1, %2;" : "=r"(u) : "f"(x1), "f"(x0));
    return u;
}
__device__ __forceinline__ float2 unpack_h2(unsigned u) {
    return __half22float2(*reinterpret_cast<__half2*>(&u));
}
__device__ __forceinline__ void mma_f16(float d[4], const unsigned a[4],
                                        unsigned b0, unsigned b1) {
    asm volatile(
        "mma.sync.aligned.m16n8k16.row.col.f32.f16.f16.f32 "
        "{%0,%1,%2,%3},{%4,%5,%6,%7},{%8,%9},{%0,%1,%2,%3};"
        : "+f"(d[0]), "+f"(d[1]), "+f"(d[2]), "+f"(d[3])
        : "r"(a[0]), "r"(a[1]), "r"(a[2]), "r"(a[3]), "r"(b0), "r"(b1));
}

__global__ void __launch_bounds__(256, 2)
gab_kernel(const float* __restrict__ scene,   // (B, NP, 3)
           const float* __restrict__ poses,   // (B, NG, 7)
           const float* __restrict__ W1, const float* __restrict__ b1,
           const float* __restrict__ g1, const float* __restrict__ be1,
           const float* __restrict__ W2, const float* __restrict__ b2,
           const float* __restrict__ g2, const float* __restrict__ be2,
           const float* __restrict__ W3, const float* __restrict__ b3,
           const float* __restrict__ bscale,
           float* __restrict__ out)            // (B, NH, NG, NP)
{
    extern __shared__ __align__(16) char smraw[];
    Smem& sm = *reinterpret_cast<Smem*>(smraw);

    const int tid = threadIdx.x;

    // ---- Once-per-block prologue (all g-independent) ----
    for (int idx = tid; idx < 8 * 4 * 32; idx += 256) {
        int kb = idx >> 7, rem = idx & 127;
        int nbp = rem >> 5, ln = rem & 31;
        int tt = ln & 3, c = ln >> 2;
        int n0 = (2 * nbp) * 8 + c, n1 = (2 * nbp + 1) * 8 + c;
        int k0 = kb * 16 + 2 * tt;
        float g0 = g1[k0 + 0], g1v = g1[k0 + 1], g8 = g1[k0 + 8], g9 = g1[k0 + 9];
        unsigned x = pack_h2(g0 * W2[(k0 + 0) * 64 + n0], g1v * W2[(k0 + 1) * 64 + n0]);
        unsigned y = pack_h2(g8 * W2[(k0 + 8) * 64 + n0], g9 * W2[(k0 + 9) * 64 + n0]);
        unsigned z = pack_h2(g0 * W2[(k0 + 0) * 64 + n1], g1v * W2[(k0 + 1) * 64 + n1]);
        unsigned w = pack_h2(g8 * W2[(k0 + 8) * 64 + n1], g9 * W2[(k0 + 9) * 64 + n1]);
        sm.Bp[kb][nbp][ln] = make_uint4(x, y, z, w);
    }
    for (int idx = tid; idx < 8 * 32; idx += 256) {
        int kbp = idx >> 5, ln = idx & 31;
        int tt = ln & 3, c = ln >> 2;
        int k0 = 2 * tt, k1 = 2 * tt + 1;
        int n0 = (2 * kbp) * 8 + c, n1 = (2 * kbp + 1) * 8 + c;
        // W1' rows: 0-3 = W1, 4 = b1, 5-7 = 0
        float w00 = (k0 < 4) ? W1[k0 * 128 + n0] : (k0 == 4 ? b1[n0] : 0.f);
        float w01 = (k1 < 4) ? W1[k1 * 128 + n0] : (k1 == 4 ? b1[n0] : 0.f);
        float w10 = (k0 < 4) ? W1[k0 * 128 + n1] : (k0 == 4 ? b1[n1] : 0.f);
        float w11 = (k1 < 4) ? W1[k1 * 128 + n1] : (k1 == 4 ? b1[n1] : 0.f);
        unsigned h0, l0, h1, l1;
        split2h(w00, w01, h0, l0);
        split2h(w10, w11, h1, l1);
        sm.W1p[kbp][ln] = make_uint4(h0, l0, h1, l1);
    }
    if (tid < 64) {
        float G = 0.f, E = 0.f;
        #pragma unroll 8
        for (int k = 0; k < 128; ++k) {
            float w = W2[k * 64 + tid];
            G = fmaf(g1[k], w, G);
            E = fmaf(be1[k], w, E);
        }
        sm.Gs[tid] = G;
        sm.EBs[tid] = E + b2[tid];
    }
    // Stage first item's scene chunk into buffer 0
    {
        int item0 = blockIdx.x;
        if (item0 < NITEMS && tid < PITEM) {
            int bb = item0 >> 9;
            int p0 = (item0 & 63) << 6;
            const float* spp = scene + ((size_t)bb * NP + p0 + tid) * 3;
            sm.sp[0][tid] = make_float4(spp[0], spp[1], spp[2], 0.f);
        }
    }
    __syncthreads();

    const int wid = tid >> 5, lane = tid & 31;
    const int t = lane & 3, gg = lane >> 2;   // mma fragment coords

    // ---- G/EB register cache (fp16x2 per nb, cols 2t,2t+1) ----
    unsigned Greg[8], EBreg[8];
    #pragma unroll
    for (int nb = 0; nb < 8; ++nb) {
        Greg[nb]  = pack_h2(sm.Gs[nb * 8 + 2 * t],  sm.Gs[nb * 8 + 2 * t + 1]);
        EBreg[nb] = pack_h2(sm.EBs[nb * 8 + 2 * t], sm.EBs[nb * 8 + 2 * t + 1]);
    }

    // ---- Stage-D B-fragments: A3 = g2 (*) W3, 2-term fp16, n = gg (g-independent) ----
    unsigned bDh0[4], bDh1[4], bDl0[4], bDl1[4];
    #pragma unroll
    for (int kb2 = 0; kb2 < 4; ++kb2) {
        int k0 = kb2 * 16 + 2 * t;
        float a0 = __ldg(g2 + k0 + 0) * __ldg(W3 + (k0 + 0) * 8 + gg);
        float a1 = __ldg(g2 + k0 + 1) * __ldg(W3 + (k0 + 1) * 8 + gg);
        float a2 = __ldg(g2 + k0 + 8) * __ldg(W3 + (k0 + 8) * 8 + gg);
        float a3 = __ldg(g2 + k0 + 9) * __ldg(W3 + (k0 + 9) * 8 + gg);
        split2h(a0, a1, bDh0[kb2], bDl0[kb2]);
        split2h(a2, a3, bDh1[kb2], bDl1[kb2]);
    }

    // ---- Per-head fold constants for heads h0 = 2t, h1 = 2t+1 (g-independent) ----
    float K2a = 0.f, K2b = 0.f, K1a = 0.f, K1b = 0.f;
    #pragma unroll 8
    for (int c = 0; c < 64; ++c) {
        float2 w = *reinterpret_cast<const float2*>(W3 + c * 8 + 2 * t);
        float gc = __ldg(g2 + c), bc = __ldg(be2 + c);
        K2a = fmaf(gc, w.x, K2a); K2b = fmaf(gc, w.y, K2b);
        K1a = fmaf(bc, w.x, K1a); K1b = fmaf(bc, w.y, K1b);
    }
    const float bsa = __ldg(bscale + 2 * t), bsb = __ldg(bscale + 2 * t + 1);
    const float C0a = (K1a + __ldg(b3 + 2 * t)) * bsa;
    const float C0b = (K1b + __ldg(b3 + 2 * t + 1)) * bsb;

    // ---- Persistent item loop: static stride schedule ----
    int bufn = 0;
    for (int item = blockIdx.x; item < NITEMS; item += PBLKS, bufn ^= 1) {
        __syncthreads();   // sp[bufn] staged & visible; prev readers of sp[bufn^1] done

        // Prefetch next item's scene chunk into the alternate buffer
        int nxt = item + PBLKS;
        if (nxt < NITEMS && tid < PITEM) {
            int bbn = nxt >> 9;
            int p0n = (nxt & 63) << 6;
            const float* spp = scene + ((size_t)bbn * NP + p0n + tid) * 3;
            sm.sp[bufn ^ 1][tid] = make_float4(spp[0], spp[1], spp[2], 0.f);
        }

        // Decode item
        const int bb = item >> 9;
        const int rem = item & 511;
        const int g = ((rem >> 6) << 3) + wid;
        const int p0 = (rem & 63) << 6;
        const float4* spb = sm.sp[bufn];

        // Pose -> rotation (per item, per warp)
        const float* pp = poses + ((size_t)(bb * NG + g)) * 7;
        float tx = pp[0], ty = pp[1], tz = pp[2];
        float qx = pp[3], qy = pp[4], qz = pp[5], qw = pp[6];
        float inv = 1.f / (sqrtf(qx * qx + qy * qy + qz * qz + qw * qw) + 1e-8f);
        qx *= inv; qy *= inv; qz *= inv; qw *= inv;
        float xx = qx * qx, yy = qy * qy, zz = qz * qz;
        float xy = qx * qy, xz = qx * qz, yz = qy * qz;
        float wx = qw * qx, wy = qw * qy, wz = qw * qz;
        float R00 = 1.f - 2.f * (yy + zz), R01 = 2.f * (xy - wz), R02 = 2.f * (xz + wy);
        float R10 = 2.f * (xy + wz), R11 = 1.f - 2.f * (xx + zz), R12 = 2.f * (yz - wx);
        float R20 = 2.f * (xz - wy), R21 = 2.f * (yz + wx), R22 = 1.f - 2.f * (xx + yy);

        const size_t outbase = (((size_t)bb * NH) * NG + g) * NP + p0;

        for (int itl = 0; itl < PITEM / TILE; ++itl) {
            // ---- Geometry for this lane's two rows (gg, gg+8) ----
            float4 PA = spb[itl * TILE + gg];
            float4 PB = spb[itl * TILE + gg + 8];
            float rxA = PA.x - tx, ryA = PA.y - ty, rzA = PA.z - tz;
            float lxA = R00 * rxA + R10 * ryA + R20 * rzA;
            float lyA = R01 * rxA + R11 * ryA + R21 * rzA;
            float lzA = R02 * rxA + R12 * ryA + R22 * rzA;
            float ddA = sqrtf(lxA * lxA + lyA * lyA + lzA * lzA);
            float rxB = PB.x - tx, ryB = PB.y - ty, rzB = PB.z - tz;
            float lxB = R00 * rxB + R10 * ryB + R20 * rzB;
            float lyB = R01 * rxB + R11 * ryB + R21 * rzB;
            float lzB = R02 * rxB + R12 * ryB + R22 * rzB;
            float ddB = sqrtf(lxB * lxB + lyB * lyB + lzB * lzB);
            // A-frag: k cols 2t,2t+1 of feats = (lx,ly,lz,dd,1,0,0,0),
            // replicated into both K-halves of the k16 fragment.
            float s0A = (t == 0) ? lxA : (t == 1) ? lzA : (t == 2) ? 1.f : 0.f;
            float s1A = (t == 0) ? lyA : (t == 1) ? ddA : 0.f;
            float s0B = (t == 0) ? lxB : (t == 1) ? lzB : (t == 2) ? 1.f : 0.f;
            float s1B = (t == 0) ? lyB : (t == 1) ? ddB : 0.f;
            unsigned afx[4];
            afx[0] = pack_h2(s0A, s1A);
            afx[1] = pack_h2(s0B, s1B);
            afx[2] = afx[0];
            afx[3] = afx[1];

            // ---- Stage B: fused 2-term W1 in one k16 mma per n-block (16 total) ----
            // B = [W1hi ; W1lo] stacked on K; A replicates feats in both K-halves.
            unsigned afr[8][4];
            float sA = 0.f, qA = 0.f, sB = 0.f, qB = 0.f;
            #pragma unroll
            for (int kbp = 0; kbp < 8; ++kbp) {
                uint4 wb = sm.W1p[kbp][lane];
                float d0[4] = {0.f, 0.f, 0.f, 0.f};
                float d1[4] = {0.f, 0.f, 0.f, 0.f};
                mma_f16(d0, afx, wb.x, wb.y);   // feats@(W1hi + W1lo), n-block 2kbp
                mma_f16(d1, afx, wb.z, wb.w);   // n-block 2kbp+1
                float v0 = fmaxf(d0[0], 0.f), v1 = fmaxf(d0[1], 0.f);
                float v2 = fmaxf(d0[2], 0.f), v3 = fmaxf(d0[3], 0.f);
                float v4 = fmaxf(d1[0], 0.f), v5 = fmaxf(d1[1], 0.f);
                float v6 = fmaxf(d1[2], 0.f), v7 = fmaxf(d1[3], 0.f);
                sA += (v0 + v1) + (v4 + v5);
                qA = fmaf(v0, v0, fmaf(v1, v1, fmaf(v4, v4, fmaf(v5, v5, qA))));
                sB += (v2 + v3) + (v6 + v7);
                qB = fmaf(v2, v2, fmaf(v3, v3, fmaf(v6, v6, fmaf(v7, v7, qB))));
                afr[kbp][0] = pack_h2(v0, v1);
                afr[kbp][1] = pack_h2(v2, v3);
                afr[kbp][2] = pack_h2(v4, v5);
                afr[kbp][3] = pack_h2(v6, v7);
            }
            // LN1 stats over 128 cols: reduce across t-quad
            #pragma unroll
            for (int o = 1; o <= 2; o <<= 1) {
                sA += __shfl_xor_sync(0xffffffffu, sA, o);
                qA += __shfl_xor_sync(0xffffffffu, qA, o);
                sB += __shfl_xor_sync(0xffffffffu, sB, o);
                qB += __shfl_xor_sync(0xffffffffu, qB, o);
            }
            float mu1A = sA * (1.f / 128.f);
            float rs1A = rsqrtf(fmaxf(qA * (1.f / 128.f) - mu1A * mu1A, 0.f) + 1e-5f);
            float ng1A = -mu1A * rs1A;
            float mu1B = sB * (1.f / 128.f);
            float rs1B = rsqrtf(fmaxf(qB * (1.f / 128.f) - mu1B * mu1B, 0.f) + 1e-5f);
            float ng1B = -mu1B * rs1B;

            // ---- Stage C: a16 @ W2' (single fp16 both sides), wide B loads ----
            float d[8][4];
            #pragma unroll
            for (int nb = 0; nb < 8; ++nb) { d[nb][0] = d[nb][1] = d[nb][2] = d[nb][3] = 0.f; }
            #pragma unroll
            for (int kb = 0; kb < 8; ++kb) {
                #pragma unroll
                for (int nbp = 0; nbp < 4; ++nbp) {
                    uint4 bp = sm.Bp[kb][nbp][lane];
                    mma_f16(d[2 * nbp],     afr[kb], bp.x, bp.y);
                    mma_f16(d[2 * nbp + 1], afr[kb], bp.z, bp.w);
                }
            }

            // ---- Epilogue (LN1-fold) + Stage D chaining (dual accumulators) ----
            float dddh[4] = {0.f, 0.f, 0.f, 0.f};
            float dddl[4] = {0.f, 0.f, 0.f, 0.f};
            float sg = 0.f, qg = 0.f, sh = 0.f, qh = 0.f;
            #pragma unroll
            for (int kb2 = 0; kb2 < 4; ++kb2) {
                const int nb0 = 2 * kb2, nb1 = 2 * kb2 + 1;
                float2 G0 = unpack_h2(Greg[nb0]), E0 = unpack_h2(EBreg[nb0]);
                float2 G1 = unpack_h2(Greg[nb1]), E1 = unpack_h2(EBreg[nb1]);
                // v = relu(rs1*d + ng1*G + EB)
                float v00 = fmaxf(fmaf(rs1A, d[nb0][0], fmaf(ng1A, G0.x, E0.x)), 0.f);
                float v01 = fmaxf(fmaf(rs1A, d[nb0][1], fmaf(ng1A, G0.y, E0.y)), 0.f);
                float v10 = fmaxf(fmaf(rs1B, d[nb0][2], fmaf(ng1B, G0.x, E0.x)), 0.f);
                float v11 = fmaxf(fmaf(rs1B, d[nb0][3], fmaf(ng1B, G0.y, E0.y)), 0.f);
                float v20 = fmaxf(fmaf(rs1A, d[nb1][0], fmaf(ng1A, G1.x, E1.x)), 0.f);
                float v21 = fmaxf(fmaf(rs1A, d[nb1][1], fmaf(ng1A, G1.y, E1.y)), 0.f);
                float v30 = fmaxf(fmaf(rs1B, d[nb1][2], fmaf(ng1B, G1.x, E1.x)), 0.f);
                float v31 = fmaxf(fmaf(rs1B, d[nb1][3], fmaf(ng1B, G1.y, E1.y)), 0.f);
                sg += (v00 + v01) + (v20 + v21);
                qg = fmaf(v00, v00, fmaf(v01, v01, fmaf(v20, v20, fmaf(v21, v21, qg))));
                sh += (v10 + v11) + (v30 + v31);
                qh = fmaf(v10, v10, fmaf(v11, v11, fmaf(v30, v30, fmaf(v31, v31, qh))));
                unsigned av[4];
                av[0] = pack_h2(v00, v01);
                av[1] = pack_h2(v10, v11);
                av[2] = pack_h2(v20, v21);
                av[3] = pack_h2(v30, v31);
                mma_f16(dddh, av, bDh0[kb2], bDh1[kb2]);   // v * A3hi
                mma_f16(dddl, av, bDl0[kb2], bDl1[kb2]);   // v * A3lo
            }
            #pragma unroll
            for (int o = 1; o <= 2; o <<= 1) {
                sg += __shfl_xor_sync(0xffffffffu, sg, o);
                qg += __shfl_xor_sync(0xffffffffu, qg, o);
                sh += __shfl_xor_sync(0xffffffffu, sh, o);
                qh += __shfl_xor_sync(0xffffffffu, qh, o);
            }
            float muA = sg * (1.f / 64.f);
            float rsA = rsqrtf(fmaxf(qg * (1.f / 64.f) - muA * muA, 0.f) + 1e-5f);
            float muB = sh * (1.f / 64.f);
            float rsB = rsqrtf(fmaxf(qh * (1.f / 64.f) - muB * muB, 0.f) + 1e-5f);

            // fold LN2 and write directly: out = (S - mu*K2)*rs*bs + C0
            {
                const int pw = itl * TILE;
                float* oA = out + outbase + (size_t)(2 * t) * (NG * NP) + pw;
                float* oB = out + outbase + (size_t)(2 * t + 1) * (NG * NP) + pw;
                float m1 = rsA * bsa, m2 = rsA * bsb;
                float m3 = rsB * bsa, m4 = rsB * bsb;
                oA[gg]     = fmaf(dddh[0] + dddl[0], m1, fmaf(-muA * m1, K2a, C0a));
                oB[gg]     = fmaf(dddh[1] + dddl[1], m2, fmaf(-muA * m2, K2b, C0b));
                oA[gg + 8] = fmaf(dddh[2] + dddl[2], m3, fmaf(-muB * m3, K2a, C0a));
                oB[gg + 8] = fmaf(dddh[3] + dddl[3], m4, fmaf(-muB * m4, K2b, C0b));
            }
        }
    }
}

extern "C" void kernel_launch(void* const* d_in, const int* in_sizes, int n_in,
                              void* d_out, int out_size) {
    // metadata order: grasp_tokens, scene_points, grasp_poses, W1, b1, g1, beta1,
    //                 W2, b2, g2, beta2, W3, b3, bias_scale
    const float* scene  = (const float*)d_in[1];
    const float* poses  = (const float*)d_in[2];
    const float* W1     = (const float*)d_in[3];
    const float* b1     = (const float*)d_in[4];
    const float* g1     = (const float*)d_in[5];
    const float* be1    = (const float*)d_in[6];
    const float* W2     = (const float*)d_in[7];
    const float* b2     = (const float*)d_in[8];
    const float* g2     = (const float*)d_in[9];
    const float* be2    = (const float*)d_in[10];
    const float* W3     = (const float*)d_in[11];
    const float* b3     = (const float*)d_in[12];
    const float* bscale = (const float*)d_in[13];
    float* out = (float*)d_out;

    cudaFuncSetAttribute(gab_kernel, cudaFuncAttributeMaxDynamicSharedMemorySize,
                         (int)sizeof(Smem));
    gab_kernel<<<PBLKS, 256, sizeof(Smem)>>>(scene, poses, W1, b1, g1, be1,
                                             W2, b2, g2, be2, W3, b3, bscale, out);
}

// round 14
// speedup vs baseline: 1.3219x; 1.0578x over previous
#include <cuda_runtime.h>
#include <cuda_fp16.h>
#include <cstdint>

// Problem dims (fixed by setup_inputs)
#define BATCH 4
#define NG 64
#define NH 8
#define NP 4096
#define TILE 16
#define PITEM 64              // points per work item (4 tiles = 2 dual-tile passes)
#define NITEMS 2048           // 4 b * 8 gchunks * 64 pchunks
#define PBLKS 296             // 148 SMs * 2 blocks -> one full wave

struct __align__(16) Smem {
    uint4  Bp[8][4][32];      // W2' frags, nb-paired                      16 KB
    uint4  W1p[8][32];        // W1' frags {h0,l0,h1,l1}                    4 KB
    float4 sp[2][PITEM];      // scene points, double-buffered              2 KB
    uint4  bDp[4][32];        // stage-D A3 frags {h0,h1,l0,l1}             2 KB
    uint2  GEp[8][4];         // {G, EB} fp16x2 per (nb, t)                256 B
};                             // ~24.3 KB total

// fp16 split: hi + residual lo, packed fp16x2 (x0 low).
__device__ __forceinline__ void split2h(float x0, float x1, unsigned& hi, unsigned& lo) {
    asm("cvt.rn.f16x2.f32 %0, %1, %2;" : "=r"(hi) : "f"(x1), "f"(x0));
    __half2 hv = *reinterpret_cast<__half2*>(&hi);
    float2 back = __half22float2(hv);
    asm("cvt.rn.f16x2.f32 %0, %1, %2;" : "=r"(lo) : "f"(x1 - back.y), "f"(x0 - back.x));
}
__device__ __forceinline__ unsigned pack_h2(float x0, float x1) {
    unsigned u;
    asm("cvt.rn.f16x2.f32 %0, %1, %2;" : "=r"(u) : "f"(x1), "f"(x0));
    return u;
}
__device__ __forceinline__ float2 unpack_h2(unsigned u) {
    return __half22float2(*reinterpret_cast<__half2*>(&u));
}
__device__ __forceinline__ void mma_f16(float d[4], const unsigned a[4],
                                        unsigned b0, unsigned b1) {
    asm volatile(
        "mma.sync.aligned.m16n8k16.row.col.f32.f16.f16.f32 "
        "{%0,%1,%2,%3},{%4,%5,%6,%7},{%8,%9},{%0,%1,%2,%3};"
        : "+f"(d[0]), "+f"(d[1]), "+f"(d[2]), "+f"(d[3])
        : "r"(a[0]), "r"(a[1]), "r"(a[2]), "r"(a[3]), "r"(b0), "r"(b1));
}

__global__ void __launch_bounds__(256, 2)
gab_kernel(const float* __restrict__ scene,   // (B, NP, 3)
           const float* __restrict__ poses,   // (B, NG, 7)
           const float* __restrict__ W1, const float* __restrict__ b1,
           const float* __restrict__ g1, const float* __restrict__ be1,
           const float* __restrict__ W2, const float* __restrict__ b2,
           const float* __restrict__ g2, const float* __restrict__ be2,
           const float* __restrict__ W3, const float* __restrict__ b3,
           const float* __restrict__ bscale,
           float* __restrict__ out)            // (B, NH, NG, NP)
{
    extern __shared__ __align__(16) char smraw[];
    Smem& sm = *reinterpret_cast<Smem*>(smraw);

    const int tid = threadIdx.x;

    // ---- Once-per-block prologue (all g-independent) ----
    for (int idx = tid; idx < 8 * 4 * 32; idx += 256) {
        int kb = idx >> 7, rem = idx & 127;
        int nbp = rem >> 5, ln = rem & 31;
        int tt = ln & 3, c = ln >> 2;
        int n0 = (2 * nbp) * 8 + c, n1 = (2 * nbp + 1) * 8 + c;
        int k0 = kb * 16 + 2 * tt;
        float g0 = g1[k0 + 0], g1v = g1[k0 + 1], g8 = g1[k0 + 8], g9 = g1[k0 + 9];
        unsigned x = pack_h2(g0 * W2[(k0 + 0) * 64 + n0], g1v * W2[(k0 + 1) * 64 + n0]);
        unsigned y = pack_h2(g8 * W2[(k0 + 8) * 64 + n0], g9 * W2[(k0 + 9) * 64 + n0]);
        unsigned z = pack_h2(g0 * W2[(k0 + 0) * 64 + n1], g1v * W2[(k0 + 1) * 64 + n1]);
        unsigned w = pack_h2(g8 * W2[(k0 + 8) * 64 + n1], g9 * W2[(k0 + 9) * 64 + n1]);
        sm.Bp[kb][nbp][ln] = make_uint4(x, y, z, w);
    }
    for (int idx = tid; idx < 8 * 32; idx += 256) {
        int kbp = idx >> 5, ln = idx & 31;
        int tt = ln & 3, c = ln >> 2;
        int k0 = 2 * tt, k1 = 2 * tt + 1;
        int n0 = (2 * kbp) * 8 + c, n1 = (2 * kbp + 1) * 8 + c;
        // W1' rows: 0-3 = W1, 4 = b1, 5-7 = 0
        float w00 = (k0 < 4) ? W1[k0 * 128 + n0] : (k0 == 4 ? b1[n0] : 0.f);
        float w01 = (k1 < 4) ? W1[k1 * 128 + n0] : (k1 == 4 ? b1[n0] : 0.f);
        float w10 = (k0 < 4) ? W1[k0 * 128 + n1] : (k0 == 4 ? b1[n1] : 0.f);
        float w11 = (k1 < 4) ? W1[k1 * 128 + n1] : (k1 == 4 ? b1[n1] : 0.f);
        unsigned h0, l0, h1, l1;
        split2h(w00, w01, h0, l0);
        split2h(w10, w11, h1, l1);
        sm.W1p[kbp][ln] = make_uint4(h0, l0, h1, l1);
    }
    if (tid < 128) {      // stage-D A3 fragments
        int kb2 = tid >> 5, ln = tid & 31;
        int tt = ln & 3, gg2 = ln >> 2;
        int k0 = kb2 * 16 + 2 * tt;
        float a0 = g2[k0 + 0] * W3[(k0 + 0) * 8 + gg2];
        float a1 = g2[k0 + 1] * W3[(k0 + 1) * 8 + gg2];
        float a2 = g2[k0 + 8] * W3[(k0 + 8) * 8 + gg2];
        float a3 = g2[k0 + 9] * W3[(k0 + 9) * 8 + gg2];
        unsigned h0, l0, h1, l1;
        split2h(a0, a1, h0, l0);
        split2h(a2, a3, h1, l1);
        sm.bDp[kb2][ln] = make_uint4(h0, h1, l0, l1);
    }
    if (tid >= 128 && tid < 160) {   // G/EB fold vectors
        int j = tid - 128;
        int nb = j >> 2, tt = j & 3;
        int n0 = nb * 8 + 2 * tt, n1 = n0 + 1;
        float G0 = 0.f, G1 = 0.f, E0 = 0.f, E1 = 0.f;
        #pragma unroll 4
        for (int k = 0; k < 128; ++k) {
            float gk = g1[k], bk = be1[k];
            float w0 = W2[k * 64 + n0], w1 = W2[k * 64 + n1];
            G0 = fmaf(gk, w0, G0); G1 = fmaf(gk, w1, G1);
            E0 = fmaf(bk, w0, E0); E1 = fmaf(bk, w1, E1);
        }
        sm.GEp[nb][tt] = make_uint2(pack_h2(G0, G1),
                                    pack_h2(E0 + b2[n0], E1 + b2[n1]));
    }
    // Stage first item's scene chunk into buffer 0
    {
        int item0 = blockIdx.x;
        if (item0 < NITEMS && tid < PITEM) {
            int bb = item0 >> 9;
            int p0 = (item0 & 63) << 6;
            const float* spp = scene + ((size_t)bb * NP + p0 + tid) * 3;
            sm.sp[0][tid] = make_float4(spp[0], spp[1], spp[2], 0.f);
        }
    }
    __syncthreads();

    const int wid = tid >> 5, lane = tid & 31;
    const int t = lane & 3, gg = lane >> 2;   // mma fragment coords

    // ---- Per-head fold constants for heads h0 = 2t, h1 = 2t+1 (g-independent) ----
    float K2a = 0.f, K2b = 0.f, K1a = 0.f, K1b = 0.f;
    #pragma unroll 8
    for (int c = 0; c < 64; ++c) {
        float2 w = *reinterpret_cast<const float2*>(W3 + c * 8 + 2 * t);
        float gc = __ldg(g2 + c), bc = __ldg(be2 + c);
        K2a = fmaf(gc, w.x, K2a); K2b = fmaf(gc, w.y, K2b);
        K1a = fmaf(bc, w.x, K1a); K1b = fmaf(bc, w.y, K1b);
    }
    const float bsa = __ldg(bscale + 2 * t), bsb = __ldg(bscale + 2 * t + 1);
    const float C0a = (K1a + __ldg(b3 + 2 * t)) * bsa;
    const float C0b = (K1b + __ldg(b3 + 2 * t + 1)) * bsb;

    // ---- Persistent item loop: static stride schedule ----
    int bufn = 0;
    for (int item = blockIdx.x; item < NITEMS; item += PBLKS, bufn ^= 1) {
        __syncthreads();   // sp[bufn] staged & visible; prev readers of sp[bufn^1] done

        // Prefetch next item's scene chunk into the alternate buffer
        int nxt = item + PBLKS;
        if (nxt < NITEMS && tid < PITEM) {
            int bbn = nxt >> 9;
            int p0n = (nxt & 63) << 6;
            const float* spp = scene + ((size_t)bbn * NP + p0n + tid) * 3;
            sm.sp[bufn ^ 1][tid] = make_float4(spp[0], spp[1], spp[2], 0.f);
        }

        // Decode item
        const int bb = item >> 9;
        const int rem = item & 511;
        const int g = ((rem >> 6) << 3) + wid;
        const int p0 = (rem & 63) << 6;
        const float4* spb = sm.sp[bufn];

        // Pose -> rotation (per item, per warp)
        const float* pp = poses + ((size_t)(bb * NG + g)) * 7;
        float tx = pp[0], ty = pp[1], tz = pp[2];
        float qx = pp[3], qy = pp[4], qz = pp[5], qw = pp[6];
        float inv = 1.f / (sqrtf(qx * qx + qy * qy + qz * qz + qw * qw) + 1e-8f);
        qx *= inv; qy *= inv; qz *= inv; qw *= inv;
        float xx = qx * qx, yy = qy * qy, zz = qz * qz;
        float xy = qx * qy, xz = qx * qz, yz = qy * qz;
        float wx = qw * qx, wy = qw * qy, wz = qw * qz;
        float R00 = 1.f - 2.f * (yy + zz), R01 = 2.f * (xy - wz), R02 = 2.f * (xz + wy);
        float R10 = 2.f * (xy + wz), R11 = 1.f - 2.f * (xx + zz), R12 = 2.f * (yz - wx);
        float R20 = 2.f * (xz - wy), R21 = 2.f * (yz + wx), R22 = 1.f - 2.f * (xx + yy);

        const size_t outbase = (((size_t)bb * NH) * NG + g) * NP + p0;

        #pragma unroll
        for (int itp = 0; itp < 2; ++itp) {   // dual-tile passes: tiles 2itp, 2itp+1
            // ---- Geometry + A-frags for both tiles ----
            unsigned afx0[4], afx1[4];
            #pragma unroll
            for (int u = 0; u < 2; ++u) {
                int base = (2 * itp + u) * TILE;
                float4 PA = spb[base + gg];
                float4 PB = spb[base + gg + 8];
                float rxA = PA.x - tx, ryA = PA.y - ty, rzA = PA.z - tz;
                float lxA = R00 * rxA + R10 * ryA + R20 * rzA;
                float lyA = R01 * rxA + R11 * ryA + R21 * rzA;
                float lzA = R02 * rxA + R12 * ryA + R22 * rzA;
                float ddA = sqrtf(lxA * lxA + lyA * lyA + lzA * lzA);
                float rxB = PB.x - tx, ryB = PB.y - ty, rzB = PB.z - tz;
                float lxB = R00 * rxB + R10 * ryB + R20 * rzB;
                float lyB = R01 * rxB + R11 * ryB + R21 * rzB;
                float lzB = R02 * rxB + R12 * ryB + R22 * rzB;
                float ddB = sqrtf(lxB * lxB + lyB * lyB + lzB * lzB);
                float s0A = (t == 0) ? lxA : (t == 1) ? lzA : (t == 2) ? 1.f : 0.f;
                float s1A = (t == 0) ? lyA : (t == 1) ? ddA : 0.f;
                float s0B = (t == 0) ? lxB : (t == 1) ? lzB : (t == 2) ? 1.f : 0.f;
                float s1B = (t == 0) ? lyB : (t == 1) ? ddB : 0.f;
                unsigned* afx = u ? afx1 : afx0;
                afx[0] = pack_h2(s0A, s1A);
                afx[1] = pack_h2(s0B, s1B);
                afx[2] = afx[0];
                afx[3] = afx[1];
            }

            // ---- Fused B+C over kb: one weight sweep feeds BOTH tiles ----
            float d0[8][4], d1[8][4];
            #pragma unroll
            for (int nb = 0; nb < 8; ++nb) {
                d0[nb][0] = d0[nb][1] = d0[nb][2] = d0[nb][3] = 0.f;
                d1[nb][0] = d1[nb][1] = d1[nb][2] = d1[nb][3] = 0.f;
            }
            float sA0 = 0.f, qA0 = 0.f, sB0 = 0.f, qB0 = 0.f;
            float sA1 = 0.f, qA1 = 0.f, sB1 = 0.f, qB1 = 0.f;

            #pragma unroll
            for (int kb = 0; kb < 8; ++kb) {
                uint4 wb = sm.W1p[kb][lane];
                float e0[4] = {0.f, 0.f, 0.f, 0.f};
                float f0[4] = {0.f, 0.f, 0.f, 0.f};
                float e1[4] = {0.f, 0.f, 0.f, 0.f};
                float f1[4] = {0.f, 0.f, 0.f, 0.f};
                mma_f16(e0, afx0, wb.x, wb.y);   // tile0, n-block 2kb
                mma_f16(f0, afx0, wb.z, wb.w);   // tile0, n-block 2kb+1
                mma_f16(e1, afx1, wb.x, wb.y);   // tile1
                mma_f16(f1, afx1, wb.z, wb.w);
                // relu + stats + pack (tile0)
                float v0 = fmaxf(e0[0], 0.f), v1 = fmaxf(e0[1], 0.f);
                float v2 = fmaxf(e0[2], 0.f), v3 = fmaxf(e0[3], 0.f);
                float v4 = fmaxf(f0[0], 0.f), v5 = fmaxf(f0[1], 0.f);
                float v6 = fmaxf(f0[2], 0.f), v7 = fmaxf(f0[3], 0.f);
                sA0 += (v0 + v1) + (v4 + v5);
                qA0 = fmaf(v0, v0, fmaf(v1, v1, fmaf(v4, v4, fmaf(v5, v5, qA0))));
                sB0 += (v2 + v3) + (v6 + v7);
                qB0 = fmaf(v2, v2, fmaf(v3, v3, fmaf(v6, v6, fmaf(v7, v7, qB0))));
                unsigned a0f[4];
                a0f[0] = pack_h2(v0, v1);
                a0f[1] = pack_h2(v2, v3);
                a0f[2] = pack_h2(v4, v5);
                a0f[3] = pack_h2(v6, v7);
                // relu + stats + pack (tile1)
                float u0 = fmaxf(e1[0], 0.f), u1 = fmaxf(e1[1], 0.f);
                float u2 = fmaxf(e1[2], 0.f), u3 = fmaxf(e1[3], 0.f);
                float u4 = fmaxf(f1[0], 0.f), u5 = fmaxf(f1[1], 0.f);
                float u6 = fmaxf(f1[2], 0.f), u7 = fmaxf(f1[3], 0.f);
                sA1 += (u0 + u1) + (u4 + u5);
                qA1 = fmaf(u0, u0, fmaf(u1, u1, fmaf(u4, u4, fmaf(u5, u5, qA1))));
                sB1 += (u2 + u3) + (u6 + u7);
                qB1 = fmaf(u2, u2, fmaf(u3, u3, fmaf(u6, u6, fmaf(u7, u7, qB1))));
                unsigned a1f[4];
                a1f[0] = pack_h2(u0, u1);
                a1f[1] = pack_h2(u2, u3);
                a1f[2] = pack_h2(u4, u5);
                a1f[3] = pack_h2(u6, u7);
                // stage C: one Bp load serves both tiles
                #pragma unroll
                for (int nbp = 0; nbp < 4; ++nbp) {
                    uint4 bp = sm.Bp[kb][nbp][lane];
                    mma_f16(d0[2 * nbp],     a0f, bp.x, bp.y);
                    mma_f16(d0[2 * nbp + 1], a0f, bp.z, bp.w);
                    mma_f16(d1[2 * nbp],     a1f, bp.x, bp.y);
                    mma_f16(d1[2 * nbp + 1], a1f, bp.z, bp.w);
                }
            }

            // ---- LN1 stats reduce (both tiles together) ----
            #pragma unroll
            for (int o = 1; o <= 2; o <<= 1) {
                sA0 += __shfl_xor_sync(0xffffffffu, sA0, o);
                qA0 += __shfl_xor_sync(0xffffffffu, qA0, o);
                sB0 += __shfl_xor_sync(0xffffffffu, sB0, o);
                qB0 += __shfl_xor_sync(0xffffffffu, qB0, o);
                sA1 += __shfl_xor_sync(0xffffffffu, sA1, o);
                qA1 += __shfl_xor_sync(0xffffffffu, qA1, o);
                sB1 += __shfl_xor_sync(0xffffffffu, sB1, o);
                qB1 += __shfl_xor_sync(0xffffffffu, qB1, o);
            }

            // ---- Epilogue + stage D per tile ----
            #pragma unroll
            for (int u = 0; u < 2; ++u) {
                float sA = u ? sA1 : sA0, qA = u ? qA1 : qA0;
                float sB = u ? sB1 : sB0, qB = u ? qB1 : qB0;
                float mu1A = sA * (1.f / 128.f);
                float rs1A = rsqrtf(fmaxf(qA * (1.f / 128.f) - mu1A * mu1A, 0.f) + 1e-5f);
                float ng1A = -mu1A * rs1A;
                float mu1B = sB * (1.f / 128.f);
                float rs1B = rsqrtf(fmaxf(qB * (1.f / 128.f) - mu1B * mu1B, 0.f) + 1e-5f);
                float ng1B = -mu1B * rs1B;

                float dddh[4] = {0.f, 0.f, 0.f, 0.f};
                float dddl[4] = {0.f, 0.f, 0.f, 0.f};
                float sg = 0.f, qg = 0.f, sh = 0.f, qh = 0.f;
                #pragma unroll
                for (int kb2 = 0; kb2 < 4; ++kb2) {
                    const int nb0 = 2 * kb2, nb1 = 2 * kb2 + 1;
                    uint2 ge0 = sm.GEp[nb0][t];
                    uint2 ge1 = sm.GEp[nb1][t];
                    float2 G0 = unpack_h2(ge0.x), E0 = unpack_h2(ge0.y);
                    float2 G1 = unpack_h2(ge1.x), E1 = unpack_h2(ge1.y);
                    const float (*dd)[4] = u ? d1 : d0;
                    // v = relu(rs1*d + ng1*G + EB)
                    float v00 = fmaxf(fmaf(rs1A, dd[nb0][0], fmaf(ng1A, G0.x, E0.x)), 0.f);
                    float v01 = fmaxf(fmaf(rs1A, dd[nb0][1], fmaf(ng1A, G0.y, E0.y)), 0.f);
                    float v10 = fmaxf(fmaf(rs1B, dd[nb0][2], fmaf(ng1B, G0.x, E0.x)), 0.f);
                    float v11 = fmaxf(fmaf(rs1B, dd[nb0][3], fmaf(ng1B, G0.y, E0.y)), 0.f);
                    float v20 = fmaxf(fmaf(rs1A, dd[nb1][0], fmaf(ng1A, G1.x, E1.x)), 0.f);
                    float v21 = fmaxf(fmaf(rs1A, dd[nb1][1], fmaf(ng1A, G1.y, E1.y)), 0.f);
                    float v30 = fmaxf(fmaf(rs1B, dd[nb1][2], fmaf(ng1B, G1.x, E1.x)), 0.f);
                    float v31 = fmaxf(fmaf(rs1B, dd[nb1][3], fmaf(ng1B, G1.y, E1.y)), 0.f);
                    sg += (v00 + v01) + (v20 + v21);
                    qg = fmaf(v00, v00, fmaf(v01, v01, fmaf(v20, v20, fmaf(v21, v21, qg))));
                    sh += (v10 + v11) + (v30 + v31);
                    qh = fmaf(v10, v10, fmaf(v11, v11, fmaf(v30, v30, fmaf(v31, v31, qh))));
                    unsigned av[4];
                    av[0] = pack_h2(v00, v01);
                    av[1] = pack_h2(v10, v11);
                    av[2] = pack_h2(v20, v21);
                    av[3] = pack_h2(v30, v31);
                    uint4 bd = sm.bDp[kb2][lane];
                    mma_f16(dddh, av, bd.x, bd.y);   // v * A3hi
                    mma_f16(dddl, av, bd.z, bd.w);   // v * A3lo
                }
                #pragma unroll
                for (int o = 1; o <= 2; o <<= 1) {
                    sg += __shfl_xor_sync(0xffffffffu, sg, o);
                    qg += __shfl_xor_sync(0xffffffffu, qg, o);
                    sh += __shfl_xor_sync(0xffffffffu, sh, o);
                    qh += __shfl_xor_sync(0xffffffffu, qh, o);
                }
                float muA = sg * (1.f / 64.f);
                float rsA = rsqrtf(fmaxf(qg * (1.f / 64.f) - muA * muA, 0.f) + 1e-5f);
                float muB = sh * (1.f / 64.f);
                float rsB = rsqrtf(fmaxf(qh * (1.f / 64.f) - muB * muB, 0.f) + 1e-5f);

                // fold LN2 and write: out = (S - mu*K2)*rs*bs + C0
                const int pw = (2 * itp + u) * TILE;
                float* oA = out + outbase + (size_t)(2 * t) * (NG * NP) + pw;
                float* oB = out + outbase + (size_t)(2 * t + 1) * (NG * NP) + pw;
                float m1 = rsA * bsa, m2 = rsA * bsb;
                float m3 = rsB * bsa, m4 = rsB * bsb;
                oA[gg]     = fmaf(dddh[0] + dddl[0], m1, fmaf(-muA * m1, K2a, C0a));
                oB[gg]     = fmaf(dddh[1] + dddl[1], m2, fmaf(-muA * m2, K2b, C0b));
                oA[gg + 8] = fmaf(dddh[2] + dddl[2], m3, fmaf(-muB * m3, K2a, C0a));
                oB[gg + 8] = fmaf(dddh[3] + dddl[3], m4, fmaf(-muB * m4, K2b, C0b));
            }
        }
    }
}

extern "C" void kernel_launch(void* const* d_in, const int* in_sizes, int n_in,
                              void* d_out, int out_size) {
    // metadata order: grasp_tokens, scene_points, grasp_poses, W1, b1, g1, beta1,
    //                 W2, b2, g2, beta2, W3, b3, bias_scale
    const float* scene  = (const float*)d_in[1];
    const float* poses  = (const float*)d_in[2];
    const float* W1     = (const float*)d_in[3];
    const float* b1     = (const float*)d_in[4];
    const float* g1     = (const float*)d_in[5];
    const float* be1    = (const float*)d_in[6];
    const float* W2     = (const float*)d_in[7];
    const float* b2     = (const float*)d_in[8];
    const float* g2     = (const float*)d_in[9];
    const float* be2    = (const float*)d_in[10];
    const float* W3     = (const float*)d_in[11];
    const float* b3     = (const float*)d_in[12];
    const float* bscale = (const float*)d_in[13];
    float* out = (float*)d_out;

    cudaFuncSetAttribute(gab_kernel, cudaFuncAttributeMaxDynamicSharedMemorySize,
                         (int)sizeof(Smem));
    gab_kernel<<<PBLKS, 256, sizeof(Smem)>>>(scene, poses, W1, b1, g1, be1,
                                             W2, b2, g2, be2, W3, b3, bscale, out);
}